// round 13
// baseline (speedup 1.0000x reference)
#include <cuda_runtime.h>
#include <cuda_fp16.h>
#include <mma.h>
#include <cstdint>

using namespace nvcuda;

// Arch-specific (sm_10xa) feature gate: tcgen05/TMEM only exist on 'a' targets.
#if defined(__CUDA_ARCH_FEAT_SM103_ALL) || defined(__CUDA_ARCH_FEAT_SM100_ALL) || defined(__CUDA_ARCH_SPECIFIC__)
#define HAS_TC 1
#else
#define HAS_TC 0
#endif

// Problem constants
constexpr int Bn = 4096;
constexpr int Nn = 8192;
constexpr int Dn = 1024;
constexpr float DROP_SCALE = 1.0f / 0.75f;
constexpr float EPS = 1e-5f;

// tcgen05 tiling: CTA computes 128 (M) x 256 (N), K-tile = 64 fp16, 4 stages.
// All fp16 operands live in gmem as PRE-TILED, PRE-SWIZZLED blocks:
//   A tile = 128 rows x 64 k = 16KB (SW128), B tile = 256 rows x 64 k = 32KB.
// Mainloop loads are single-thread cp.async.bulk + mbarrier complete_tx.
constexpr int TM = 128;
constexpr int TN = 256;
constexpr int TK = 64;
constexpr uint32_t A_TILE = 16384;
constexpr uint32_t B_TILE = 32768;
constexpr uint32_t IDESC = (1u << 4) | ((TN / 8) << 17) | ((TM / 16) << 24);

// smem: header 1KB (tmem ptr @0, full mbars @64+8s, done mbars @128+8s), 4 stages
constexpr uint32_t STAGE_BYTES = A_TILE + B_TILE;            // 49152
constexpr uint32_t SM_TILES = 1024;
constexpr uint32_t SMEM_BYTES = SM_TILES + 4 * STAGE_BYTES;  // 197632

// Device-global scratch (no cudaMalloc). Tiled fp16 operand arrays:
//  g_h   : gemm1 A tiles, index rb*128 + kt   (rb<32, kt<128)
//  g_Wh  : gemm1 B tiles, index cb*128 + kt   (cb<4,  kt<128)
//  g_Wt  : gemm2 B tiles, index nb*16  + kt   (nb<32, kt<16)
//  g_ench: gemm2 A tiles, index rb*16  + kt   (rb<32, kt<16)
__device__ __align__(1024) __half g_h[(size_t)Bn * Nn];
__device__ __align__(1024) __half g_Wh[(size_t)Dn * Nn];
__device__ __align__(1024) __half g_Wt[(size_t)Nn * Dn];
__device__ __align__(1024) __half g_ench[(size_t)Bn * Dn];
__device__ float g_enc[(size_t)Bn * Dn];     // linear fp32 enc (for LN)
__device__ float g_errp[(size_t)Bn * 64];
__device__ float g_cntp[(size_t)Bn * 64];
__device__ float g_lossp[32];

__device__ __forceinline__ uint32_t smem_u32(const void* p) {
    uint32_t a;
    asm("{ .reg .u64 t; cvta.to.shared.u64 t, %1; cvt.u32.u64 %0, t; }" : "=r"(a) : "l"(p));
    return a;
}
__device__ __forceinline__ uint32_t swz(uint32_t bo) {        // SW128 swizzle
    return bo ^ ((bo >> 3) & 0x70);
}

#if HAS_TC
// ---------------------------------------------------------------------------
// tcgen05 / TMA helpers (sm_103a only)
// ---------------------------------------------------------------------------
__device__ __forceinline__ bool elect_one() {
    uint32_t pred;
    asm volatile("{\n\t.reg .pred p;\n\telect.sync _|p, 0xFFFFFFFF;\n\tselp.b32 %0, 1, 0, p;\n\t}"
                 : "=r"(pred));
    return pred != 0;
}
__device__ __forceinline__ void mbar_init(uint32_t a, uint32_t cnt) {
    asm volatile("mbarrier.init.shared.b64 [%0], %1;" :: "r"(a), "r"(cnt) : "memory");
}
__device__ __forceinline__ void mbar_wait(uint32_t a, uint32_t parity) {
    asm volatile(
        "{\n\t.reg .pred P;\n\t"
        "WL_%=:\n\t"
        "mbarrier.try_wait.parity.acquire.cta.shared::cta.b64 P, [%0], %1, 0x989680;\n\t"
        "@P bra WD_%=;\n\t"
        "bra WL_%=;\n\t"
        "WD_%=:\n\t}"
        :: "r"(a), "r"(parity) : "memory");
}
__device__ __forceinline__ void mbar_expect_tx(uint32_t a, uint32_t bytes) {
    asm volatile("mbarrier.arrive.expect_tx.shared.b64 _, [%0], %1;"
                 :: "r"(a), "r"(bytes) : "memory");
}
__device__ __forceinline__ void bulk_cp(uint32_t dst, const void* src,
                                        uint32_t bytes, uint32_t mbar) {
    asm volatile(
        "cp.async.bulk.shared::cta.global.mbarrier::complete_tx::bytes [%0], [%1], %2, [%3];"
        :: "r"(dst), "l"(src), "r"(bytes), "r"(mbar) : "memory");
}
__device__ __forceinline__ void mma_f16_ss(uint32_t d, uint64_t ad, uint64_t bd,
                                           uint32_t idesc, bool acc) {
    uint32_t en = acc ? 1u : 0u;
    asm volatile(
        "{\n\t.reg .pred p;\n\tsetp.ne.u32 p, %5, 0;\n\t"
        "tcgen05.mma.cta_group::1.kind::f16 [%0], %1, %2, %3, {%4, %4, %4, %4}, p;\n\t}"
        :: "r"(d), "l"(ad), "l"(bd), "r"(idesc), "r"(0u), "r"(en) : "memory");
}
__device__ __forceinline__ void tc_commit(uint32_t mbar) {
    asm volatile(
        "tcgen05.commit.cta_group::1.mbarrier::arrive::one.shared::cluster.b64 [%0];"
        :: "r"(mbar) : "memory");
}
__device__ __forceinline__ uint64_t mk_desc(uint32_t addr) {
    constexpr uint64_t BASE = (uint64_t(2) << 61) | (uint64_t(1) << 46) |
                              (uint64_t(64) << 32) | (uint64_t(1) << 16);
    return BASE | ((uint64_t)(addr >> 4) & 0x3FFF);
}
#define TC_ALLOC(sm, n)   asm volatile("tcgen05.alloc.cta_group::1.sync.aligned.shared::cta.b32 [%0], %1;" :: "r"(sm), "r"(n) : "memory")
#define TC_DEALLOC(t, n)  asm volatile("tcgen05.dealloc.cta_group::1.sync.aligned.b32 %0, %1;" :: "r"(t), "r"(n))
#define TC_RELINQ()       asm volatile("tcgen05.relinquish_alloc_permit.cta_group::1.sync.aligned;")
#define TC_FENCE_AFTER()  asm volatile("tcgen05.fence::after_thread_sync;" ::: "memory")
#define TC_FENCE_BEFORE() asm volatile("tcgen05.fence::before_thread_sync;" ::: "memory")
#define TC_WAIT_LD()      asm volatile("tcgen05.wait::ld.sync.aligned;" ::: "memory")

#define LDTM_X32(r, a) \
    asm volatile("tcgen05.ld.sync.aligned.32x32b.x32.b32 " \
        "{%0,%1,%2,%3,%4,%5,%6,%7,%8,%9,%10,%11,%12,%13,%14,%15," \
        "%16,%17,%18,%19,%20,%21,%22,%23,%24,%25,%26,%27,%28,%29,%30,%31}, [%32];" \
        : "=r"((r)[0]),"=r"((r)[1]),"=r"((r)[2]),"=r"((r)[3]),"=r"((r)[4]),"=r"((r)[5]), \
          "=r"((r)[6]),"=r"((r)[7]),"=r"((r)[8]),"=r"((r)[9]),"=r"((r)[10]),"=r"((r)[11]), \
          "=r"((r)[12]),"=r"((r)[13]),"=r"((r)[14]),"=r"((r)[15]),"=r"((r)[16]),"=r"((r)[17]), \
          "=r"((r)[18]),"=r"((r)[19]),"=r"((r)[20]),"=r"((r)[21]),"=r"((r)[22]),"=r"((r)[23]), \
          "=r"((r)[24]),"=r"((r)[25]),"=r"((r)[26]),"=r"((r)[27]),"=r"((r)[28]),"=r"((r)[29]), \
          "=r"((r)[30]),"=r"((r)[31]) : "r"(a))

// ---------------------------------------------------------------------------
// Bulk-TMA mainloop, LAG-1 refill: C[128x256] = A*B^T over tiles*64 K.
// Warp 0 runs the pipeline; warps 1-7 park on __syncthreads.
// Iteration kt: full-wait(s=kt&3) -> issue 4 MMAs(tile kt) -> commit(done[s])
//   -> [refill] done-wait(tile kt-1, stage sr=(kt-1)&3) -> bulk load tile kt+3
//      into stage sr.
// The done-wait targets the commit issued ONE iteration earlier (not the one
// just issued), so the tensor pipe always has the current MMA queued while
// the warp services loads: period = max(MMA exec, L2 supply, overhead).
// ---------------------------------------------------------------------------
__device__ __forceinline__ uint32_t gemm_mainloop_tma(
    const char* At, size_t a0, const char* Bt, size_t b0, int tiles, uint32_t sb)
{
    const int tid = threadIdx.x;
    const int wid = tid >> 5;

    if (wid == 0) TC_ALLOC(sb, 256);
    if (tid == 0) {
        #pragma unroll
        for (int s = 0; s < 4; ++s) {
            mbar_init(sb + 64 + 8 * s, 1);    // full
            mbar_init(sb + 128 + 8 * s, 1);   // done
        }
        asm volatile("fence.proxy.async.shared::cta;" ::: "memory");
    }
    __syncthreads();
    if (wid == 0) TC_RELINQ();
    uint32_t tmem;
    asm volatile("ld.shared.b32 %0, [%1];" : "=r"(tmem) : "r"(sb));

    if (wid == 0) {
        const bool el = elect_one();
        if (el) {   // prologue: pre-fill all 4 stages (tiles >= 4 always)
            #pragma unroll
            for (int i = 0; i < 4; ++i) {
                const uint32_t stage = sb + SM_TILES + i * STAGE_BYTES;
                mbar_expect_tx(sb + 64 + 8 * i, STAGE_BYTES);
                bulk_cp(stage,          At + (a0 + i) * A_TILE, A_TILE, sb + 64 + 8 * i);
                bulk_cp(stage + A_TILE, Bt + (b0 + i) * B_TILE, B_TILE, sb + 64 + 8 * i);
            }
        }
        uint32_t fph = 0, dph = 0;
        for (int kt = 0; kt < tiles; ++kt) {
            const int s = kt & 3;
            mbar_wait(sb + 64 + 8 * s, (fph >> s) & 1u);    // whole warp
            fph ^= 1u << s;
            asm volatile("fence.proxy.async.shared::cta;" ::: "memory");
            if (el) {
                const uint32_t stage = sb + SM_TILES + s * STAGE_BYTES;
                const uint64_t ad = mk_desc(stage);
                const uint64_t bd = mk_desc(stage + A_TILE);
                #pragma unroll
                for (int ks = 0; ks < 4; ++ks)
                    mma_f16_ss(tmem, ad + 2 * ks, bd + 2 * ks, IDESC, (kt > 0) || ks > 0);
                tc_commit(sb + 128 + 8 * s);
                // LAG-1 refill: load tile kt+3 into stage (kt-1)&3, guarded by
                // the commit of tile kt-1 (issued last iteration -> ~0 wait).
                if (kt >= 1 && kt + 3 < tiles) {
                    const int sr = (kt - 1) & 3;
                    const uint32_t rstage = sb + SM_TILES + sr * STAGE_BYTES;
                    mbar_wait(sb + 128 + 8 * sr, (dph >> sr) & 1u);
                    dph ^= 1u << sr;
                    mbar_expect_tx(sb + 64 + 8 * sr, STAGE_BYTES);
                    bulk_cp(rstage,          At + (a0 + kt + 3) * A_TILE, A_TILE, sb + 64 + 8 * sr);
                    bulk_cp(rstage + A_TILE, Bt + (b0 + kt + 3) * B_TILE, B_TILE, sb + 64 + 8 * sr);
                }
            }
        }
        // Elected lane: wait the LAST commit (tracks ALL prior MMAs). Refill
        // waits consumed stage (tiles-1)&3 completions only for tiles <= tiles-5,
        // so its dph bit is the parity of tile tiles-1's completion.
        if (el) {
            const int sl = (tiles - 1) & 3;
            mbar_wait(sb + 128 + 8 * sl, (dph >> sl) & 1u);
        }
    }
    __syncthreads();          // release warps 1-7 only after MMAs all done
    TC_FENCE_AFTER();
    return tmem;
}
#endif  // HAS_TC

// ---------------------------------------------------------------------------
// Fallback (non-'a' PTX pass): wmma fp16 reading the TILED+SWIZZLED layout.
// C[128x128] = A[128 x K] * B(rows brow_off..+128)[x K]^T into Cs.
// ---------------------------------------------------------------------------
__device__ __forceinline__ void fb_gemm128(
    const char* At, size_t a0, const char* Bt, size_t b0, int brow_off,
    int K, char* smem, float* Cs)
{
    __half* As = reinterpret_cast<__half*>(smem);
    __half* Bs = reinterpret_cast<__half*>(smem + 128 * 40 * 2);
    const int tid = threadIdx.x;
    const int wid = tid >> 5;
    const int wm = wid & 1, wn = wid >> 1;

    wmma::fragment<wmma::accumulator, 16, 16, 16, float> acc[4][2];
    #pragma unroll
    for (int i = 0; i < 4; i++)
        #pragma unroll
        for (int j = 0; j < 2; j++)
            wmma::fill_fragment(acc[i][j], 0.0f);

    for (int kt = 0; kt < K / 32; ++kt) {
        const int kb = kt * 32;
        #pragma unroll
        for (int i = 0; i < 2; ++i) {
            const int v = tid + i * 256;
            const int r = v >> 2, k0 = kb + (v & 3) * 8;
            const int tile = k0 >> 6, kin = k0 & 63;
            *reinterpret_cast<uint4*>(&As[r * 40 + (v & 3) * 8]) =
                *reinterpret_cast<const uint4*>(
                    At + (a0 + tile) * A_TILE + swz((uint32_t)(r * 128 + kin * 2)));
            *reinterpret_cast<uint4*>(&Bs[r * 40 + (v & 3) * 8]) =
                *reinterpret_cast<const uint4*>(
                    Bt + (b0 + tile) * B_TILE + swz((uint32_t)((brow_off + r) * 128 + kin * 2)));
        }
        __syncthreads();
        #pragma unroll
        for (int kk = 0; kk < 32; kk += 16) {
            wmma::fragment<wmma::matrix_a, 16, 16, 16, __half, wmma::row_major> af[4];
            wmma::fragment<wmma::matrix_b, 16, 16, 16, __half, wmma::col_major> bf[2];
            #pragma unroll
            for (int fm = 0; fm < 4; fm++)
                wmma::load_matrix_sync(af[fm], &As[(wm * 64 + fm * 16) * 40 + kk], 40);
            #pragma unroll
            for (int fn = 0; fn < 2; fn++)
                wmma::load_matrix_sync(bf[fn], &Bs[(wn * 32 + fn * 16) * 40 + kk], 40);
            #pragma unroll
            for (int fm = 0; fm < 4; fm++)
                #pragma unroll
                for (int fn = 0; fn < 2; fn++)
                    wmma::mma_sync(acc[fm][fn], af[fm], bf[fn], acc[fm][fn]);
        }
        __syncthreads();
    }
    #pragma unroll
    for (int fm = 0; fm < 4; fm++)
        #pragma unroll
        for (int fn = 0; fn < 2; fn++)
            wmma::store_matrix_sync(&Cs[(wm * 64 + fm * 16) * 132 + wn * 32 + fn * 16],
                                    acc[fm][fn], 132, wmma::mem_row_major);
    __syncthreads();
}

// ---------------------------------------------------------------------------
// GEMM1: enc = tanh(h @ Wh^T + b1) -> g_enc (fp32, linear) + g_ench (tiled)
// grid: (Dn/TN=4, Bn/TM=32), 256 threads
// ---------------------------------------------------------------------------
__global__ __launch_bounds__(256) void gemm1_kernel(const float* __restrict__ b1)
{
    extern __shared__ __align__(1024) char smem[];
    const int rb = blockIdx.y;
    const int cb = blockIdx.x;
    const int row0 = rb * TM;
    const int col0 = cb * TN;
    const int tid = threadIdx.x;
    const int wid = tid >> 5;
    const int lane = tid & 31;

#if HAS_TC
    const uint32_t sb = smem_u32(smem);
    const uint32_t tmem = gemm_mainloop_tma((const char*)g_h, (size_t)rb * 128,
                                            (const char*)g_Wh, (size_t)cb * 128,
                                            Nn / TK, sb);
    const int team = wid >> 2;
    const int r = ((wid & 3) << 5) + lane;
    const size_t grow = (size_t)(row0 + r);
    #pragma unroll
    for (int chunk = 0; chunk < 4; ++chunk) {
        const int c0 = team * 128 + chunk * 32;
        uint32_t regs[32];
        LDTM_X32(regs, tmem + c0);
        TC_WAIT_LD();
        #pragma unroll
        for (int j = 0; j < 32; j += 2) {
            const int d = col0 + c0 + j;
            const float e0 = tanhf(__uint_as_float(regs[j])     + b1[d]);
            const float e1 = tanhf(__uint_as_float(regs[j + 1]) + b1[d + 1]);
            g_enc[grow * Dn + d]     = e0;
            g_enc[grow * Dn + d + 1] = e1;
            const uint32_t bo = (uint32_t)(r * 128 + (d & 63) * 2);
            *reinterpret_cast<__half2*>(
                (char*)g_ench + (size_t)(rb * 16 + (d >> 6)) * A_TILE + swz(bo)) =
                __floats2half2_rn(e0, e1);
        }
    }
    TC_FENCE_BEFORE();
    __syncthreads();
    if (wid == 0) TC_DEALLOC(tmem, 256);
#else
    float* Cs = reinterpret_cast<float*>(smem);
    for (int hf = 0; hf < 2; ++hf) {
        fb_gemm128((const char*)g_h, (size_t)rb * 128,
                   (const char*)g_Wh, (size_t)cb * 128, hf * 128, Nn, smem, Cs);
        #pragma unroll 4
        for (int t = 0; t < 32; ++t) {
            const int p = tid + t * 256;
            const int r = p >> 6, c2 = (p & 63) * 2;
            const int d = col0 + hf * 128 + c2;
            const size_t grow = (size_t)(row0 + r);
            const float e0 = tanhf(Cs[r * 132 + c2]     + b1[d]);
            const float e1 = tanhf(Cs[r * 132 + c2 + 1] + b1[d + 1]);
            g_enc[grow * Dn + d]     = e0;
            g_enc[grow * Dn + d + 1] = e1;
            const uint32_t bo = (uint32_t)(r * 128 + (d & 63) * 2);
            *reinterpret_cast<__half2*>(
                (char*)g_ench + (size_t)(rb * 16 + (d >> 6)) * A_TILE + swz(bo)) =
                __floats2half2_rn(e0, e1);
        }
        __syncthreads();
    }
#endif
}

// ---------------------------------------------------------------------------
// GEMM2: recon = ench @ Wt^T + b2 (never stored); fused masked-MSE partials
// grid: (Nn/TN=32, Bn/TM=32)
// ---------------------------------------------------------------------------
__global__ __launch_bounds__(256) void gemm2_kernel(
    const float* __restrict__ x, const float* __restrict__ b2)
{
    extern __shared__ __align__(1024) char smem[];
    const int rb = blockIdx.y;
    const int nb = blockIdx.x;
    const int row0 = rb * TM;
    const int n0 = nb * TN;
    const int tid = threadIdx.x;
    const int wid = tid >> 5;
    const int lane = tid & 31;

#if HAS_TC
    const uint32_t sb = smem_u32(smem);
    const uint32_t tmem = gemm_mainloop_tma((const char*)g_ench, (size_t)rb * 16,
                                            (const char*)g_Wt, (size_t)nb * 16,
                                            Dn / TK, sb);
    const int team = wid >> 2;
    const int r = ((wid & 3) << 5) + lane;
    const size_t grow = (size_t)(row0 + r);
    float err = 0.f, cnt = 0.f;
    #pragma unroll
    for (int chunk = 0; chunk < 4; ++chunk) {
        const int c0 = team * 128 + chunk * 32;
        uint32_t regs[32];
        LDTM_X32(regs, tmem + c0);
        TC_WAIT_LD();
        const float* xr = x + grow * Nn + n0 + c0;
        const float* b2r = b2 + n0 + c0;
        #pragma unroll
        for (int j = 0; j < 32; ++j) {
            const float recon = __uint_as_float(regs[j]) + b2r[j];
            const float xv = xr[j];
            if (xv != 0.0f) {
                const float d = xv - recon;
                err += d * d;
                cnt += 1.0f;
            }
        }
    }
    g_errp[grow * 64 + nb * 2 + team] = err;
    g_cntp[grow * 64 + nb * 2 + team] = cnt;

    TC_FENCE_BEFORE();
    __syncthreads();
    if (wid == 0) TC_DEALLOC(tmem, 256);
#else
    float* Cs = reinterpret_cast<float*>(smem);
    for (int hf = 0; hf < 2; ++hf) {
        fb_gemm128((const char*)g_ench, (size_t)rb * 16,
                   (const char*)g_Wt, (size_t)nb * 16, hf * 128, Dn, smem, Cs);
        for (int rr = 0; rr < 16; ++rr) {
            const int r = wid * 16 + rr;
            const size_t brow = (size_t)(row0 + r);
            float err = 0.f, cnt = 0.f;
            #pragma unroll
            for (int s4 = 0; s4 < 4; ++s4) {
                const int c = s4 * 32 + lane;
                const float recon = Cs[r * 132 + c] + b2[n0 + hf * 128 + c];
                const float xv = x[brow * Nn + n0 + hf * 128 + c];
                if (xv != 0.0f) {
                    const float d = xv - recon;
                    err += d * d;
                    cnt += 1.0f;
                }
            }
            #pragma unroll
            for (int o = 16; o; o >>= 1) {
                err += __shfl_xor_sync(0xffffffffu, err, o);
                cnt += __shfl_xor_sync(0xffffffffu, cnt, o);
            }
            if (lane == 0) {
                g_errp[brow * 64 + nb * 2 + hf] = err;
                g_cntp[brow * 64 + nb * 2 + hf] = cnt;
            }
        }
        __syncthreads();
    }
#endif
}

// ---------------------------------------------------------------------------
// Pre-pass: dropout-scale x -> fp16, write g_h in tiled+swizzled layout
// ---------------------------------------------------------------------------
__global__ void conv_h_kernel(const float4* __restrict__ x, const float4* __restrict__ m)
{
    const size_t i = (size_t)blockIdx.x * blockDim.x + threadIdx.x;   // 8M float4
    const int row = (int)(i >> 11);               // Nn/4 = 2048 float4 per row
    const int n0 = ((int)i & 2047) * 4;
    const float4 xv = x[i], mv = m[i];
    __half2 h0 = __floats2half2_rn(xv.x * mv.x * DROP_SCALE, xv.y * mv.y * DROP_SCALE);
    __half2 h1 = __floats2half2_rn(xv.z * mv.z * DROP_SCALE, xv.w * mv.w * DROP_SCALE);
    const int rb = row >> 7, r = row & 127;
    const int kt = n0 >> 6, c = n0 & 63;
    const uint32_t bo = (uint32_t)(r * 128 + c * 2);                  // %8 == 0
    char* p = (char*)g_h + (size_t)(rb * 128 + kt) * A_TILE + swz(bo);
    uint2 v;
    v.x = *reinterpret_cast<uint32_t*>(&h0);
    v.y = *reinterpret_cast<uint32_t*>(&h1);
    *reinterpret_cast<uint2*>(p) = v;
}

// W prep: read W once; emit g_Wh (tiled, d-major rows) and g_Wt (tiled, n-major rows)
__global__ void wprep_kernel(const float* __restrict__ W)
{
    __shared__ __half t[32][33];
    const int n0 = blockIdx.x * 32, d0 = blockIdx.y * 32;
    const int tx = threadIdx.x, ty = threadIdx.y;
    #pragma unroll
    for (int i = ty; i < 32; i += 8) {
        const int d = d0 + i, n = n0 + tx;
        const __half v = __float2half_rn(W[(size_t)d * Nn + n]);
        const uint32_t bo = (uint32_t)((d & 255) * 128 + (n & 63) * 2);
        *reinterpret_cast<__half*>(
            (char*)g_Wh + (size_t)((d >> 8) * 128 + (n >> 6)) * B_TILE + swz(bo)) = v;
        t[i][tx] = v;
    }
    __syncthreads();
    #pragma unroll
    for (int i = ty; i < 32; i += 8) {
        const int n = n0 + i, d = d0 + tx;
        const uint32_t bo = (uint32_t)((n & 255) * 128 + (d & 63) * 2);
        *reinterpret_cast<__half*>(
            (char*)g_Wt + (size_t)((n >> 8) * 16 + (d >> 6)) * B_TILE + swz(bo)) = t[tx][i];
    }
}

// ---------------------------------------------------------------------------
// LayerNorm over D per row -> out[0 : B*D)
// ---------------------------------------------------------------------------
__global__ __launch_bounds__(256) void ln_kernel(
    const float* __restrict__ gamma, const float* __restrict__ beta,
    float* __restrict__ out)
{
    const int row = blockIdx.x;
    const int tid = threadIdx.x;
    const float* rp = g_enc + (size_t)row * Dn;
    float e[4], s = 0.f, ss = 0.f;
    #pragma unroll
    for (int j = 0; j < 4; j++) {
        e[j] = rp[tid + j * 256];
        s += e[j];
        ss += e[j] * e[j];
    }
    #pragma unroll
    for (int o = 16; o; o >>= 1) {
        s  += __shfl_xor_sync(0xffffffffu, s, o);
        ss += __shfl_xor_sync(0xffffffffu, ss, o);
    }
    __shared__ float r1[8], r2[8];
    __shared__ float sh_mu, sh_rstd;
    if ((tid & 31) == 0) { r1[tid >> 5] = s; r2[tid >> 5] = ss; }
    __syncthreads();
    if (tid == 0) {
        float ts = 0.f, tss = 0.f;
        #pragma unroll
        for (int k = 0; k < 8; k++) { ts += r1[k]; tss += r2[k]; }
        const float mu = ts * (1.0f / Dn);
        const float var = tss * (1.0f / Dn) - mu * mu;
        sh_mu = mu;
        sh_rstd = rsqrtf(var + EPS);
    }
    __syncthreads();
    const float mu = sh_mu, rstd = sh_rstd;
    #pragma unroll
    for (int j = 0; j < 4; j++) {
        const int d = tid + j * 256;
        out[(size_t)row * Dn + d] = (e[j] - mu) * rstd * gamma[d] + beta[d];
    }
}

// ---------------------------------------------------------------------------
// Loss reduction (fixed order, no atomics)
// ---------------------------------------------------------------------------
__global__ void reduce1_kernel()
{
    const int row = blockIdx.x * 128 + threadIdx.x;
    float err = 0.f, cnt = 0.f;
    #pragma unroll 8
    for (int j = 0; j < 64; ++j) {
        err += g_errp[(size_t)row * 64 + j];
        cnt += g_cntp[(size_t)row * 64 + j];
    }
    __shared__ float sh[128];
    sh[threadIdx.x] = err / cnt;
    __syncthreads();
    for (int s = 64; s > 0; s >>= 1) {
        if (threadIdx.x < s) sh[threadIdx.x] += sh[threadIdx.x + s];
        __syncthreads();
    }
    if (threadIdx.x == 0) g_lossp[blockIdx.x] = sh[0];
}

__global__ void reduce2_kernel(float* __restrict__ out)
{
    float v = g_lossp[threadIdx.x];
    #pragma unroll
    for (int o = 16; o; o >>= 1) v += __shfl_xor_sync(0xffffffffu, v, o);
    if (threadIdx.x == 0) out[(size_t)Bn * Dn] = v;
}

// ---------------------------------------------------------------------------
// Entry. Inputs: x, drop_mask, W, b1, b2, gamma, beta.
// Output: final [B, D] then recon_loss scalar at out[B*D].
// ---------------------------------------------------------------------------
extern "C" void kernel_launch(void* const* d_in, const int* in_sizes, int n_in,
                              void* d_out, int out_size)
{
    const float* x     = (const float*)d_in[0];
    const float* mask  = (const float*)d_in[1];
    const float* W     = (const float*)d_in[2];
    const float* b1    = (const float*)d_in[3];
    const float* b2    = (const float*)d_in[4];
    const float* gamma = (const float*)d_in[5];
    const float* beta  = (const float*)d_in[6];
    float* out = (float*)d_out;

    cudaFuncSetAttribute(gemm1_kernel, cudaFuncAttributeMaxDynamicSharedMemorySize, SMEM_BYTES);
    cudaFuncSetAttribute(gemm2_kernel, cudaFuncAttributeMaxDynamicSharedMemorySize, SMEM_BYTES);

    conv_h_kernel<<<(Bn * (Nn / 4)) / 256, 256>>>((const float4*)x, (const float4*)mask);
    wprep_kernel<<<dim3(Nn / 32, Dn / 32), dim3(32, 8)>>>(W);
    gemm1_kernel<<<dim3(Dn / TN, Bn / TM), 256, SMEM_BYTES>>>(b1);
    ln_kernel<<<Bn, 256>>>(gamma, beta, out);
    gemm2_kernel<<<dim3(Nn / TN, Bn / TM), 256, SMEM_BYTES>>>(x, b2);
    reduce1_kernel<<<32, 128>>>();
    reduce2_kernel<<<1, 32>>>(out);
}

// round 14
// speedup vs baseline: 1.3683x; 1.3683x over previous
#include <cuda_runtime.h>
#include <cuda_fp16.h>
#include <mma.h>
#include <cstdint>

using namespace nvcuda;

// Arch-specific (sm_10xa) feature gate: tcgen05/TMEM only exist on 'a' targets.
#if defined(__CUDA_ARCH_FEAT_SM103_ALL) || defined(__CUDA_ARCH_FEAT_SM100_ALL) || defined(__CUDA_ARCH_SPECIFIC__)
#define HAS_TC 1
#else
#define HAS_TC 0
#endif

// Problem constants
constexpr int Bn = 4096;
constexpr int Nn = 8192;
constexpr int Dn = 1024;
constexpr float DROP_SCALE = 1.0f / 0.75f;
constexpr float EPS = 1e-5f;

// tcgen05 tiling. GEMM1: CTA = 128(M) x 256(N), 4 stages of (A 16K + B 32K).
// GEMM2: CTA = 256(M, two 128-row blocks sharing B) x 256(N), 3 stages of
// (A0 16K + A1 16K + B 32K) — dual TMEM accumulators (cols 0-255 / 256-511).
// All fp16 operands are PRE-TILED, PRE-SWIZZLED 16/32KB blocks in gmem;
// mainloop loads are single-thread cp.async.bulk + mbarrier complete_tx.
constexpr int TM = 128;
constexpr int TN = 256;
constexpr int TK = 64;
constexpr uint32_t A_TILE = 16384;
constexpr uint32_t B_TILE = 32768;
constexpr uint32_t IDESC = (1u << 4) | ((TN / 8) << 17) | ((TM / 16) << 24);

constexpr uint32_t STAGE1_BYTES = A_TILE + B_TILE;             // 49152 (gemm1)
constexpr uint32_t STAGE2_BYTES = 2 * A_TILE + B_TILE;         // 65536 (gemm2)
constexpr uint32_t SM_TILES = 1024;
constexpr uint32_t SMEM_BYTES = SM_TILES + 4 * STAGE1_BYTES;   // 197632
static_assert(SM_TILES + 3 * STAGE2_BYTES <= SMEM_BYTES, "gemm2 stages fit");

// Device-global scratch (no cudaMalloc). Tiled fp16 operand arrays:
//  g_h   : gemm1 A tiles, index rb*128 + kt   (rb<32, kt<128)
//  g_Wh  : gemm1 B tiles, index cb*128 + kt   (cb<4,  kt<128)
//  g_Wt  : gemm2 B tiles, index nb*16  + kt   (nb<32, kt<16)
//  g_ench: gemm2 A tiles, index rb*16  + kt   (rb<32, kt<16)
__device__ __align__(1024) __half g_h[(size_t)Bn * Nn];
__device__ __align__(1024) __half g_Wh[(size_t)Dn * Nn];
__device__ __align__(1024) __half g_Wt[(size_t)Nn * Dn];
__device__ __align__(1024) __half g_ench[(size_t)Bn * Dn];
__device__ float g_enc[(size_t)Bn * Dn];     // linear fp32 enc (for LN)
__device__ float g_errp[(size_t)Bn * 64];
__device__ float g_cntp[(size_t)Bn * 64];
__device__ float g_lossp[32];

__device__ __forceinline__ uint32_t smem_u32(const void* p) {
    uint32_t a;
    asm("{ .reg .u64 t; cvta.to.shared.u64 t, %1; cvt.u32.u64 %0, t; }" : "=r"(a) : "l"(p));
    return a;
}
__device__ __forceinline__ uint32_t swz(uint32_t bo) {        // SW128 swizzle
    return bo ^ ((bo >> 3) & 0x70);
}

#if HAS_TC
// ---------------------------------------------------------------------------
// tcgen05 / TMA helpers (sm_103a only)
// ---------------------------------------------------------------------------
__device__ __forceinline__ bool elect_one() {
    uint32_t pred;
    asm volatile("{\n\t.reg .pred p;\n\telect.sync _|p, 0xFFFFFFFF;\n\tselp.b32 %0, 1, 0, p;\n\t}"
                 : "=r"(pred));
    return pred != 0;
}
__device__ __forceinline__ void mbar_init(uint32_t a, uint32_t cnt) {
    asm volatile("mbarrier.init.shared.b64 [%0], %1;" :: "r"(a), "r"(cnt) : "memory");
}
__device__ __forceinline__ void mbar_wait(uint32_t a, uint32_t parity) {
    asm volatile(
        "{\n\t.reg .pred P;\n\t"
        "WL_%=:\n\t"
        "mbarrier.try_wait.parity.acquire.cta.shared::cta.b64 P, [%0], %1, 0x989680;\n\t"
        "@P bra WD_%=;\n\t"
        "bra WL_%=;\n\t"
        "WD_%=:\n\t}"
        :: "r"(a), "r"(parity) : "memory");
}
__device__ __forceinline__ void mbar_expect_tx(uint32_t a, uint32_t bytes) {
    asm volatile("mbarrier.arrive.expect_tx.shared.b64 _, [%0], %1;"
                 :: "r"(a), "r"(bytes) : "memory");
}
__device__ __forceinline__ void bulk_cp(uint32_t dst, const void* src,
                                        uint32_t bytes, uint32_t mbar) {
    asm volatile(
        "cp.async.bulk.shared::cta.global.mbarrier::complete_tx::bytes [%0], [%1], %2, [%3];"
        :: "r"(dst), "l"(src), "r"(bytes), "r"(mbar) : "memory");
}
__device__ __forceinline__ void mma_f16_ss(uint32_t d, uint64_t ad, uint64_t bd,
                                           uint32_t idesc, bool acc) {
    uint32_t en = acc ? 1u : 0u;
    asm volatile(
        "{\n\t.reg .pred p;\n\tsetp.ne.u32 p, %5, 0;\n\t"
        "tcgen05.mma.cta_group::1.kind::f16 [%0], %1, %2, %3, {%4, %4, %4, %4}, p;\n\t}"
        :: "r"(d), "l"(ad), "l"(bd), "r"(idesc), "r"(0u), "r"(en) : "memory");
}
__device__ __forceinline__ void tc_commit(uint32_t mbar) {
    asm volatile(
        "tcgen05.commit.cta_group::1.mbarrier::arrive::one.shared::cluster.b64 [%0];"
        :: "r"(mbar) : "memory");
}
__device__ __forceinline__ uint64_t mk_desc(uint32_t addr) {
    constexpr uint64_t BASE = (uint64_t(2) << 61) | (uint64_t(1) << 46) |
                              (uint64_t(64) << 32) | (uint64_t(1) << 16);
    return BASE | ((uint64_t)(addr >> 4) & 0x3FFF);
}
#define TC_ALLOC(sm, n)   asm volatile("tcgen05.alloc.cta_group::1.sync.aligned.shared::cta.b32 [%0], %1;" :: "r"(sm), "r"(n) : "memory")
#define TC_DEALLOC(t, n)  asm volatile("tcgen05.dealloc.cta_group::1.sync.aligned.b32 %0, %1;" :: "r"(t), "r"(n))
#define TC_RELINQ()       asm volatile("tcgen05.relinquish_alloc_permit.cta_group::1.sync.aligned;")
#define TC_FENCE_AFTER()  asm volatile("tcgen05.fence::after_thread_sync;" ::: "memory")
#define TC_FENCE_BEFORE() asm volatile("tcgen05.fence::before_thread_sync;" ::: "memory")
#define TC_WAIT_LD()      asm volatile("tcgen05.wait::ld.sync.aligned;" ::: "memory")

#define LDTM_X32(r, a) \
    asm volatile("tcgen05.ld.sync.aligned.32x32b.x32.b32 " \
        "{%0,%1,%2,%3,%4,%5,%6,%7,%8,%9,%10,%11,%12,%13,%14,%15," \
        "%16,%17,%18,%19,%20,%21,%22,%23,%24,%25,%26,%27,%28,%29,%30,%31}, [%32];" \
        : "=r"((r)[0]),"=r"((r)[1]),"=r"((r)[2]),"=r"((r)[3]),"=r"((r)[4]),"=r"((r)[5]), \
          "=r"((r)[6]),"=r"((r)[7]),"=r"((r)[8]),"=r"((r)[9]),"=r"((r)[10]),"=r"((r)[11]), \
          "=r"((r)[12]),"=r"((r)[13]),"=r"((r)[14]),"=r"((r)[15]),"=r"((r)[16]),"=r"((r)[17]), \
          "=r"((r)[18]),"=r"((r)[19]),"=r"((r)[20]),"=r"((r)[21]),"=r"((r)[22]),"=r"((r)[23]), \
          "=r"((r)[24]),"=r"((r)[25]),"=r"((r)[26]),"=r"((r)[27]),"=r"((r)[28]),"=r"((r)[29]), \
          "=r"((r)[30]),"=r"((r)[31]) : "r"(a))

// ---------------------------------------------------------------------------
// GEMM1 mainloop (unchanged from best): 4 stages, lag-1 refill, warp 0 only.
// ---------------------------------------------------------------------------
__device__ __forceinline__ uint32_t gemm_mainloop_tma(
    const char* At, size_t a0, const char* Bt, size_t b0, int tiles, uint32_t sb)
{
    const int tid = threadIdx.x;
    const int wid = tid >> 5;

    if (wid == 0) TC_ALLOC(sb, 256);
    if (tid == 0) {
        #pragma unroll
        for (int s = 0; s < 4; ++s) {
            mbar_init(sb + 64 + 8 * s, 1);    // full
            mbar_init(sb + 128 + 8 * s, 1);   // done
        }
        asm volatile("fence.proxy.async.shared::cta;" ::: "memory");
    }
    __syncthreads();
    if (wid == 0) TC_RELINQ();
    uint32_t tmem;
    asm volatile("ld.shared.b32 %0, [%1];" : "=r"(tmem) : "r"(sb));

    if (wid == 0) {
        const bool el = elect_one();
        if (el) {
            #pragma unroll
            for (int i = 0; i < 4; ++i) {
                const uint32_t stage = sb + SM_TILES + i * STAGE1_BYTES;
                mbar_expect_tx(sb + 64 + 8 * i, STAGE1_BYTES);
                bulk_cp(stage,          At + (a0 + i) * A_TILE, A_TILE, sb + 64 + 8 * i);
                bulk_cp(stage + A_TILE, Bt + (b0 + i) * B_TILE, B_TILE, sb + 64 + 8 * i);
            }
        }
        uint32_t fph = 0, dph = 0;
        for (int kt = 0; kt < tiles; ++kt) {
            const int s = kt & 3;
            mbar_wait(sb + 64 + 8 * s, (fph >> s) & 1u);
            fph ^= 1u << s;
            asm volatile("fence.proxy.async.shared::cta;" ::: "memory");
            if (el) {
                const uint32_t stage = sb + SM_TILES + s * STAGE1_BYTES;
                const uint64_t ad = mk_desc(stage);
                const uint64_t bd = mk_desc(stage + A_TILE);
                #pragma unroll
                for (int ks = 0; ks < 4; ++ks)
                    mma_f16_ss(tmem, ad + 2 * ks, bd + 2 * ks, IDESC, (kt > 0) || ks > 0);
                tc_commit(sb + 128 + 8 * s);
                if (kt >= 1 && kt + 3 < tiles) {   // lag-1 refill
                    const int sr = (kt - 1) & 3;
                    const uint32_t rstage = sb + SM_TILES + sr * STAGE1_BYTES;
                    mbar_wait(sb + 128 + 8 * sr, (dph >> sr) & 1u);
                    dph ^= 1u << sr;
                    mbar_expect_tx(sb + 64 + 8 * sr, STAGE1_BYTES);
                    bulk_cp(rstage,          At + (a0 + kt + 3) * A_TILE, A_TILE, sb + 64 + 8 * sr);
                    bulk_cp(rstage + A_TILE, Bt + (b0 + kt + 3) * B_TILE, B_TILE, sb + 64 + 8 * sr);
                }
            }
        }
        if (el) {
            const int sl = (tiles - 1) & 3;
            mbar_wait(sb + 128 + 8 * sl, (dph >> sl) & 1u);
        }
    }
    __syncthreads();
    TC_FENCE_AFTER();
    return tmem;
}

// ---------------------------------------------------------------------------
// GEMM2 mainloop: dual accumulator (two 128-row A blocks share one B tile).
// 3 stages of (A0 16K | A1 16K | B 32K) = 64KB. Lag-1 refill: at iter kt,
// refill stage (kt-1)%3 with tile kt+2 guarded by commit of tile kt-1.
// D0 at tmem cols 0-255 (rows rb0), D1 at cols 256-511 (rows rb1).
// ---------------------------------------------------------------------------
__device__ __forceinline__ uint32_t gemm2_mainloop_tma(
    const char* At, size_t a00, size_t a01, const char* Bt, size_t b0,
    int tiles, uint32_t sb)
{
    const int tid = threadIdx.x;
    const int wid = tid >> 5;

    if (wid == 0) TC_ALLOC(sb, 512);
    if (tid == 0) {
        #pragma unroll
        for (int s = 0; s < 3; ++s) {
            mbar_init(sb + 64 + 8 * s, 1);    // full
            mbar_init(sb + 128 + 8 * s, 1);   // done
        }
        asm volatile("fence.proxy.async.shared::cta;" ::: "memory");
    }
    __syncthreads();
    if (wid == 0) TC_RELINQ();
    uint32_t tmem;
    asm volatile("ld.shared.b32 %0, [%1];" : "=r"(tmem) : "r"(sb));

    if (wid == 0) {
        const bool el = elect_one();
        if (el) {   // prologue: fill 3 stages (tiles >= 3)
            #pragma unroll
            for (int i = 0; i < 3; ++i) {
                const uint32_t stage = sb + SM_TILES + i * STAGE2_BYTES;
                mbar_expect_tx(sb + 64 + 8 * i, STAGE2_BYTES);
                bulk_cp(stage,              At + (a00 + i) * A_TILE, A_TILE, sb + 64 + 8 * i);
                bulk_cp(stage + A_TILE,     At + (a01 + i) * A_TILE, A_TILE, sb + 64 + 8 * i);
                bulk_cp(stage + 2 * A_TILE, Bt + (b0 + i) * B_TILE,  B_TILE, sb + 64 + 8 * i);
            }
        }
        uint32_t fph = 0, dph = 0;
        for (int kt = 0; kt < tiles; ++kt) {
            const int s = kt % 3;
            mbar_wait(sb + 64 + 8 * s, (fph >> s) & 1u);
            fph ^= 1u << s;
            asm volatile("fence.proxy.async.shared::cta;" ::: "memory");
            if (el) {
                const uint32_t stage = sb + SM_TILES + s * STAGE2_BYTES;
                const uint64_t a0d = mk_desc(stage);
                const uint64_t a1d = mk_desc(stage + A_TILE);
                const uint64_t bd  = mk_desc(stage + 2 * A_TILE);
                #pragma unroll
                for (int ks = 0; ks < 4; ++ks)
                    mma_f16_ss(tmem, a0d + 2 * ks, bd + 2 * ks, IDESC, (kt > 0) || ks > 0);
                #pragma unroll
                for (int ks = 0; ks < 4; ++ks)
                    mma_f16_ss(tmem + 256, a1d + 2 * ks, bd + 2 * ks, IDESC, (kt > 0) || ks > 0);
                tc_commit(sb + 128 + 8 * s);
                if (kt >= 1 && kt + 2 < tiles) {   // lag-1 refill
                    const int sr = (kt - 1) % 3;
                    const uint32_t rstage = sb + SM_TILES + sr * STAGE2_BYTES;
                    mbar_wait(sb + 128 + 8 * sr, (dph >> sr) & 1u);
                    dph ^= 1u << sr;
                    mbar_expect_tx(sb + 64 + 8 * sr, STAGE2_BYTES);
                    bulk_cp(rstage,              At + (a00 + kt + 2) * A_TILE, A_TILE, sb + 64 + 8 * sr);
                    bulk_cp(rstage + A_TILE,     At + (a01 + kt + 2) * A_TILE, A_TILE, sb + 64 + 8 * sr);
                    bulk_cp(rstage + 2 * A_TILE, Bt + (b0 + kt + 2) * B_TILE,  B_TILE, sb + 64 + 8 * sr);
                }
            }
        }
        if (el) {
            const int sl = (tiles - 1) % 3;
            mbar_wait(sb + 128 + 8 * sl, (dph >> sl) & 1u);
        }
    }
    __syncthreads();
    TC_FENCE_AFTER();
    return tmem;
}
#endif  // HAS_TC

// ---------------------------------------------------------------------------
// Fallback (non-'a' PTX pass): wmma fp16 reading the TILED+SWIZZLED layout.
// ---------------------------------------------------------------------------
__device__ __forceinline__ void fb_gemm128(
    const char* At, size_t a0, const char* Bt, size_t b0, int brow_off,
    int K, char* smem, float* Cs)
{
    __half* As = reinterpret_cast<__half*>(smem);
    __half* Bs = reinterpret_cast<__half*>(smem + 128 * 40 * 2);
    const int tid = threadIdx.x;
    const int wid = tid >> 5;
    const int wm = wid & 1, wn = wid >> 1;

    wmma::fragment<wmma::accumulator, 16, 16, 16, float> acc[4][2];
    #pragma unroll
    for (int i = 0; i < 4; i++)
        #pragma unroll
        for (int j = 0; j < 2; j++)
            wmma::fill_fragment(acc[i][j], 0.0f);

    for (int kt = 0; kt < K / 32; ++kt) {
        const int kb = kt * 32;
        #pragma unroll
        for (int i = 0; i < 2; ++i) {
            const int v = tid + i * 256;
            const int r = v >> 2, k0 = kb + (v & 3) * 8;
            const int tile = k0 >> 6, kin = k0 & 63;
            *reinterpret_cast<uint4*>(&As[r * 40 + (v & 3) * 8]) =
                *reinterpret_cast<const uint4*>(
                    At + (a0 + tile) * A_TILE + swz((uint32_t)(r * 128 + kin * 2)));
            *reinterpret_cast<uint4*>(&Bs[r * 40 + (v & 3) * 8]) =
                *reinterpret_cast<const uint4*>(
                    Bt + (b0 + tile) * B_TILE + swz((uint32_t)((brow_off + r) * 128 + kin * 2)));
        }
        __syncthreads();
        #pragma unroll
        for (int kk = 0; kk < 32; kk += 16) {
            wmma::fragment<wmma::matrix_a, 16, 16, 16, __half, wmma::row_major> af[4];
            wmma::fragment<wmma::matrix_b, 16, 16, 16, __half, wmma::col_major> bf[2];
            #pragma unroll
            for (int fm = 0; fm < 4; fm++)
                wmma::load_matrix_sync(af[fm], &As[(wm * 64 + fm * 16) * 40 + kk], 40);
            #pragma unroll
            for (int fn = 0; fn < 2; fn++)
                wmma::load_matrix_sync(bf[fn], &Bs[(wn * 32 + fn * 16) * 40 + kk], 40);
            #pragma unroll
            for (int fm = 0; fm < 4; fm++)
                #pragma unroll
                for (int fn = 0; fn < 2; fn++)
                    wmma::mma_sync(acc[fm][fn], af[fm], bf[fn], acc[fm][fn]);
        }
        __syncthreads();
    }
    #pragma unroll
    for (int fm = 0; fm < 4; fm++)
        #pragma unroll
        for (int fn = 0; fn < 2; fn++)
            wmma::store_matrix_sync(&Cs[(wm * 64 + fm * 16) * 132 + wn * 32 + fn * 16],
                                    acc[fm][fn], 132, wmma::mem_row_major);
    __syncthreads();
}

// ---------------------------------------------------------------------------
// GEMM1: enc = tanh(h @ Wh^T + b1) -> g_enc (fp32, linear) + g_ench (tiled)
// grid: (cb=Dn/TN=4, rb=Bn/TM=32), 256 threads
// ---------------------------------------------------------------------------
__global__ __launch_bounds__(256) void gemm1_kernel(const float* __restrict__ b1)
{
    extern __shared__ __align__(1024) char smem[];
    const int rb = blockIdx.y;
    const int cb = blockIdx.x;
    const int row0 = rb * TM;
    const int col0 = cb * TN;
    const int tid = threadIdx.x;
    const int wid = tid >> 5;
    const int lane = tid & 31;

#if HAS_TC
    const uint32_t sb = smem_u32(smem);
    const uint32_t tmem = gemm_mainloop_tma((const char*)g_h, (size_t)rb * 128,
                                            (const char*)g_Wh, (size_t)cb * 128,
                                            Nn / TK, sb);
    const int team = wid >> 2;
    const int r = ((wid & 3) << 5) + lane;
    const size_t grow = (size_t)(row0 + r);
    #pragma unroll
    for (int chunk = 0; chunk < 4; ++chunk) {
        const int c0 = team * 128 + chunk * 32;
        uint32_t regs[32];
        LDTM_X32(regs, tmem + c0);
        TC_WAIT_LD();
        #pragma unroll
        for (int j = 0; j < 32; j += 2) {
            const int d = col0 + c0 + j;
            const float e0 = tanhf(__uint_as_float(regs[j])     + b1[d]);
            const float e1 = tanhf(__uint_as_float(regs[j + 1]) + b1[d + 1]);
            g_enc[grow * Dn + d]     = e0;
            g_enc[grow * Dn + d + 1] = e1;
            const uint32_t bo = (uint32_t)(r * 128 + (d & 63) * 2);
            *reinterpret_cast<__half2*>(
                (char*)g_ench + (size_t)(rb * 16 + (d >> 6)) * A_TILE + swz(bo)) =
                __floats2half2_rn(e0, e1);
        }
    }
    TC_FENCE_BEFORE();
    __syncthreads();
    if (wid == 0) TC_DEALLOC(tmem, 256);
#else
    float* Cs = reinterpret_cast<float*>(smem);
    for (int hf = 0; hf < 2; ++hf) {
        fb_gemm128((const char*)g_h, (size_t)rb * 128,
                   (const char*)g_Wh, (size_t)cb * 128, hf * 128, Nn, smem, Cs);
        #pragma unroll 4
        for (int t = 0; t < 32; ++t) {
            const int p = tid + t * 256;
            const int r = p >> 6, c2 = (p & 63) * 2;
            const int d = col0 + hf * 128 + c2;
            const size_t grow = (size_t)(row0 + r);
            const float e0 = tanhf(Cs[r * 132 + c2]     + b1[d]);
            const float e1 = tanhf(Cs[r * 132 + c2 + 1] + b1[d + 1]);
            g_enc[grow * Dn + d]     = e0;
            g_enc[grow * Dn + d + 1] = e1;
            const uint32_t bo = (uint32_t)(r * 128 + (d & 63) * 2);
            *reinterpret_cast<__half2*>(
                (char*)g_ench + (size_t)(rb * 16 + (d >> 6)) * A_TILE + swz(bo)) =
                __floats2half2_rn(e0, e1);
        }
        __syncthreads();
    }
#endif
}

// ---------------------------------------------------------------------------
// GEMM2: recon = ench @ Wt^T + b2 (never stored); fused masked-MSE partials.
// grid: (nb=Nn/TN=32, rbp=Bn/256=16) — each CTA covers TWO 128-row blocks
// (rb0 = 2*rbp, rb1 = 2*rbp+1) sharing one B tile stream (halves B traffic).
// ---------------------------------------------------------------------------
__global__ __launch_bounds__(256) void gemm2_kernel(
    const float* __restrict__ x, const float* __restrict__ b2)
{
    extern __shared__ __align__(1024) char smem[];
    const int nb = blockIdx.x;
    const int rbp = blockIdx.y;
    const int n0 = nb * TN;
    const int tid = threadIdx.x;
    const int wid = tid >> 5;
    const int lane = tid & 31;

#if HAS_TC
    const uint32_t sb = smem_u32(smem);
    const uint32_t tmem = gemm2_mainloop_tma(
        (const char*)g_ench, (size_t)(2 * rbp) * 16, (size_t)(2 * rbp + 1) * 16,
        (const char*)g_Wt, (size_t)nb * 16, Dn / TK, sb);

    // warps 0-3: rb0 rows via D0 (cols 0-255); warps 4-7: rb1 via D1 (cols 256-511)
    const int half = wid >> 2;
    const int r = ((wid & 3) << 5) + lane;
    const size_t grow = (size_t)(rbp * 256 + half * 128 + r);
    float err = 0.f, cnt = 0.f;
    #pragma unroll
    for (int chunk = 0; chunk < 8; ++chunk) {
        const int c0 = chunk * 32;
        uint32_t regs[32];
        LDTM_X32(regs, tmem + half * 256 + c0);
        TC_WAIT_LD();
        const float* xr = x + grow * Nn + n0 + c0;
        const float* b2r = b2 + n0 + c0;
        #pragma unroll
        for (int j = 0; j < 32; ++j) {
            const float recon = __uint_as_float(regs[j]) + b2r[j];
            const float xv = xr[j];
            if (xv != 0.0f) {
                const float d = xv - recon;
                err += d * d;
                cnt += 1.0f;
            }
        }
    }
    g_errp[grow * 64 + nb * 2]     = err;
    g_errp[grow * 64 + nb * 2 + 1] = 0.0f;
    g_cntp[grow * 64 + nb * 2]     = cnt;
    g_cntp[grow * 64 + nb * 2 + 1] = 0.0f;

    TC_FENCE_BEFORE();
    __syncthreads();
    if (wid == 0) TC_DEALLOC(tmem, 512);
#else
    float* Cs = reinterpret_cast<float*>(smem);
    for (int rsub = 0; rsub < 2; ++rsub) {
        const int rb = rbp * 2 + rsub;
        for (int hf = 0; hf < 2; ++hf) {
            fb_gemm128((const char*)g_ench, (size_t)rb * 16,
                       (const char*)g_Wt, (size_t)nb * 16, hf * 128, Dn, smem, Cs);
            for (int rr = 0; rr < 16; ++rr) {
                const int r = wid * 16 + rr;
                const size_t brow = (size_t)(rb * 128 + r);
                float err = 0.f, cnt = 0.f;
                #pragma unroll
                for (int s4 = 0; s4 < 4; ++s4) {
                    const int c = s4 * 32 + lane;
                    const float recon = Cs[r * 132 + c] + b2[n0 + hf * 128 + c];
                    const float xv = x[brow * Nn + n0 + hf * 128 + c];
                    if (xv != 0.0f) {
                        const float d = xv - recon;
                        err += d * d;
                        cnt += 1.0f;
                    }
                }
                #pragma unroll
                for (int o = 16; o; o >>= 1) {
                    err += __shfl_xor_sync(0xffffffffu, err, o);
                    cnt += __shfl_xor_sync(0xffffffffu, cnt, o);
                }
                if (lane == 0) {
                    g_errp[brow * 64 + nb * 2 + hf] = err;
                    g_cntp[brow * 64 + nb * 2 + hf] = cnt;
                }
            }
            __syncthreads();
        }
    }
#endif
}

// ---------------------------------------------------------------------------
// Pre-pass: dropout-scale x -> fp16, write g_h in tiled+swizzled layout
// ---------------------------------------------------------------------------
__global__ void conv_h_kernel(const float4* __restrict__ x, const float4* __restrict__ m)
{
    const size_t i = (size_t)blockIdx.x * blockDim.x + threadIdx.x;   // 8M float4
    const int row = (int)(i >> 11);               // Nn/4 = 2048 float4 per row
    const int n0 = ((int)i & 2047) * 4;
    const float4 xv = x[i], mv = m[i];
    __half2 h0 = __floats2half2_rn(xv.x * mv.x * DROP_SCALE, xv.y * mv.y * DROP_SCALE);
    __half2 h1 = __floats2half2_rn(xv.z * mv.z * DROP_SCALE, xv.w * mv.w * DROP_SCALE);
    const int rb = row >> 7, r = row & 127;
    const int kt = n0 >> 6, c = n0 & 63;
    const uint32_t bo = (uint32_t)(r * 128 + c * 2);                  // %8 == 0
    char* p = (char*)g_h + (size_t)(rb * 128 + kt) * A_TILE + swz(bo);
    uint2 v;
    v.x = *reinterpret_cast<uint32_t*>(&h0);
    v.y = *reinterpret_cast<uint32_t*>(&h1);
    *reinterpret_cast<uint2*>(p) = v;
}

// W prep: read W once; emit g_Wh (tiled, d-major rows) and g_Wt (tiled, n-major rows)
__global__ void wprep_kernel(const float* __restrict__ W)
{
    __shared__ __half t[32][33];
    const int n0 = blockIdx.x * 32, d0 = blockIdx.y * 32;
    const int tx = threadIdx.x, ty = threadIdx.y;
    #pragma unroll
    for (int i = ty; i < 32; i += 8) {
        const int d = d0 + i, n = n0 + tx;
        const __half v = __float2half_rn(W[(size_t)d * Nn + n]);
        const uint32_t bo = (uint32_t)((d & 255) * 128 + (n & 63) * 2);
        *reinterpret_cast<__half*>(
            (char*)g_Wh + (size_t)((d >> 8) * 128 + (n >> 6)) * B_TILE + swz(bo)) = v;
        t[i][tx] = v;
    }
    __syncthreads();
    #pragma unroll
    for (int i = ty; i < 32; i += 8) {
        const int n = n0 + i, d = d0 + tx;
        const uint32_t bo = (uint32_t)((n & 255) * 128 + (d & 63) * 2);
        *reinterpret_cast<__half*>(
            (char*)g_Wt + (size_t)((n >> 8) * 16 + (d >> 6)) * B_TILE + swz(bo)) = t[tx][i];
    }
}

// ---------------------------------------------------------------------------
// LayerNorm over D per row -> out[0 : B*D)
// ---------------------------------------------------------------------------
__global__ __launch_bounds__(256) void ln_kernel(
    const float* __restrict__ gamma, const float* __restrict__ beta,
    float* __restrict__ out)
{
    const int row = blockIdx.x;
    const int tid = threadIdx.x;
    const float* rp = g_enc + (size_t)row * Dn;
    float e[4], s = 0.f, ss = 0.f;
    #pragma unroll
    for (int j = 0; j < 4; j++) {
        e[j] = rp[tid + j * 256];
        s += e[j];
        ss += e[j] * e[j];
    }
    #pragma unroll
    for (int o = 16; o; o >>= 1) {
        s  += __shfl_xor_sync(0xffffffffu, s, o);
        ss += __shfl_xor_sync(0xffffffffu, ss, o);
    }
    __shared__ float r1[8], r2[8];
    __shared__ float sh_mu, sh_rstd;
    if ((tid & 31) == 0) { r1[tid >> 5] = s; r2[tid >> 5] = ss; }
    __syncthreads();
    if (tid == 0) {
        float ts = 0.f, tss = 0.f;
        #pragma unroll
        for (int k = 0; k < 8; k++) { ts += r1[k]; tss += r2[k]; }
        const float mu = ts * (1.0f / Dn);
        const float var = tss * (1.0f / Dn) - mu * mu;
        sh_mu = mu;
        sh_rstd = rsqrtf(var + EPS);
    }
    __syncthreads();
    const float mu = sh_mu, rstd = sh_rstd;
    #pragma unroll
    for (int j = 0; j < 4; j++) {
        const int d = tid + j * 256;
        out[(size_t)row * Dn + d] = (e[j] - mu) * rstd * gamma[d] + beta[d];
    }
}

// ---------------------------------------------------------------------------
// Loss reduction (fixed order, no atomics)
// ---------------------------------------------------------------------------
__global__ void reduce1_kernel()
{
    const int row = blockIdx.x * 128 + threadIdx.x;
    float err = 0.f, cnt = 0.f;
    #pragma unroll 8
    for (int j = 0; j < 64; ++j) {
        err += g_errp[(size_t)row * 64 + j];
        cnt += g_cntp[(size_t)row * 64 + j];
    }
    __shared__ float sh[128];
    sh[threadIdx.x] = err / cnt;
    __syncthreads();
    for (int s = 64; s > 0; s >>= 1) {
        if (threadIdx.x < s) sh[threadIdx.x] += sh[threadIdx.x + s];
        __syncthreads();
    }
    if (threadIdx.x == 0) g_lossp[blockIdx.x] = sh[0];
}

__global__ void reduce2_kernel(float* __restrict__ out)
{
    float v = g_lossp[threadIdx.x];
    #pragma unroll
    for (int o = 16; o; o >>= 1) v += __shfl_xor_sync(0xffffffffu, v, o);
    if (threadIdx.x == 0) out[(size_t)Bn * Dn] = v;
}

// ---------------------------------------------------------------------------
// Entry. Inputs: x, drop_mask, W, b1, b2, gamma, beta.
// Output: final [B, D] then recon_loss scalar at out[B*D].
// NOTE launch order: gemm2 moved before ln (dependency-safe) so the fixed
// ncu capture slot lands on a GEMM instead of ln.
// ---------------------------------------------------------------------------
extern "C" void kernel_launch(void* const* d_in, const int* in_sizes, int n_in,
                              void* d_out, int out_size)
{
    const float* x     = (const float*)d_in[0];
    const float* mask  = (const float*)d_in[1];
    const float* W     = (const float*)d_in[2];
    const float* b1    = (const float*)d_in[3];
    const float* b2    = (const float*)d_in[4];
    const float* gamma = (const float*)d_in[5];
    const float* beta  = (const float*)d_in[6];
    float* out = (float*)d_out;

    cudaFuncSetAttribute(gemm1_kernel, cudaFuncAttributeMaxDynamicSharedMemorySize, SMEM_BYTES);
    cudaFuncSetAttribute(gemm2_kernel, cudaFuncAttributeMaxDynamicSharedMemorySize, SMEM_BYTES);

    conv_h_kernel<<<(Bn * (Nn / 4)) / 256, 256>>>((const float4*)x, (const float4*)mask);
    wprep_kernel<<<dim3(Nn / 32, Dn / 32), dim3(32, 8)>>>(W);
    gemm1_kernel<<<dim3(Dn / TN, Bn / TM), 256, SMEM_BYTES>>>(b1);
    gemm2_kernel<<<dim3(Nn / TN, Bn / 256), 256, SMEM_BYTES>>>(x, b2);
    ln_kernel<<<Bn, 256>>>(gamma, beta, out);
    reduce1_kernel<<<32, 128>>>();
    reduce2_kernel<<<1, 32>>>(out);
}

// round 15
// speedup vs baseline: 1.8842x; 1.3771x over previous
#include <cuda_runtime.h>
#include <cuda_fp16.h>
#include <mma.h>
#include <cstdint>

using namespace nvcuda;

// Arch-specific (sm_10xa) feature gate: tcgen05/TMEM only exist on 'a' targets.
#if defined(__CUDA_ARCH_FEAT_SM103_ALL) || defined(__CUDA_ARCH_FEAT_SM100_ALL) || defined(__CUDA_ARCH_SPECIFIC__)
#define HAS_TC 1
#else
#define HAS_TC 0
#endif

// Problem constants
constexpr int Bn = 4096;
constexpr int Nn = 8192;
constexpr int Dn = 1024;
constexpr float DROP_SCALE = 1.0f / 0.75f;
constexpr float EPS = 1e-5f;

// tcgen05 tiling. GEMM1: CTA = 128(M) x 256(N), 4 stages of (A 16K + B 32K).
// GEMM2: CTA = 256(M, two 128-row blocks sharing B) x 256(N), 3 stages of
// (A0 16K + A1 16K + B 32K) — dual TMEM accumulators (cols 0-255 / 256-511).
// Epilogues stage all strided I/O through smem (pitch 257 floats) so every
// gmem access is coalesced (the R14 profile showed the lane-stride=row
// pattern costing 32 L1 wavefronts per instruction — the dominant term).
constexpr int TM = 128;
constexpr int TN = 256;
constexpr int TK = 64;
constexpr uint32_t A_TILE = 16384;
constexpr uint32_t B_TILE = 32768;
constexpr uint32_t IDESC = (1u << 4) | ((TN / 8) << 17) | ((TM / 16) << 24);

constexpr uint32_t STAGE1_BYTES = A_TILE + B_TILE;             // 49152 (gemm1)
constexpr uint32_t STAGE2_BYTES = 2 * A_TILE + B_TILE;         // 65536 (gemm2)
constexpr uint32_t SM_TILES = 1024;
constexpr uint32_t SMEM_BYTES = SM_TILES + 4 * STAGE1_BYTES;   // 197632
static_assert(SM_TILES + 3 * STAGE2_BYTES <= SMEM_BYTES, "gemm2 stages fit");
constexpr int XP = 257;   // staging pitch in floats (257 % 32 == 1 -> no conflicts)
static_assert(SM_TILES + 128 * XP * 4 <= SMEM_BYTES, "staging fits");

// Device-global scratch (no cudaMalloc). Tiled fp16 operand arrays:
__device__ __align__(1024) __half g_h[(size_t)Bn * Nn];
__device__ __align__(1024) __half g_Wh[(size_t)Dn * Nn];
__device__ __align__(1024) __half g_Wt[(size_t)Nn * Dn];
__device__ __align__(1024) __half g_ench[(size_t)Bn * Dn];
__device__ float g_enc[(size_t)Bn * Dn];     // linear fp32 enc (for LN)
__device__ float g_errp[(size_t)Bn * 64];
__device__ float g_cntp[(size_t)Bn * 64];
__device__ float g_lossp[32];

__device__ __forceinline__ uint32_t smem_u32(const void* p) {
    uint32_t a;
    asm("{ .reg .u64 t; cvta.to.shared.u64 t, %1; cvt.u32.u64 %0, t; }" : "=r"(a) : "l"(p));
    return a;
}
__device__ __forceinline__ uint32_t swz(uint32_t bo) {        // SW128 swizzle
    return bo ^ ((bo >> 3) & 0x70);
}

#if HAS_TC
// ---------------------------------------------------------------------------
// tcgen05 / TMA helpers (sm_103a only)
// ---------------------------------------------------------------------------
__device__ __forceinline__ bool elect_one() {
    uint32_t pred;
    asm volatile("{\n\t.reg .pred p;\n\telect.sync _|p, 0xFFFFFFFF;\n\tselp.b32 %0, 1, 0, p;\n\t}"
                 : "=r"(pred));
    return pred != 0;
}
__device__ __forceinline__ void mbar_init(uint32_t a, uint32_t cnt) {
    asm volatile("mbarrier.init.shared.b64 [%0], %1;" :: "r"(a), "r"(cnt) : "memory");
}
__device__ __forceinline__ void mbar_wait(uint32_t a, uint32_t parity) {
    asm volatile(
        "{\n\t.reg .pred P;\n\t"
        "WL_%=:\n\t"
        "mbarrier.try_wait.parity.acquire.cta.shared::cta.b64 P, [%0], %1, 0x989680;\n\t"
        "@P bra WD_%=;\n\t"
        "bra WL_%=;\n\t"
        "WD_%=:\n\t}"
        :: "r"(a), "r"(parity) : "memory");
}
__device__ __forceinline__ void mbar_expect_tx(uint32_t a, uint32_t bytes) {
    asm volatile("mbarrier.arrive.expect_tx.shared.b64 _, [%0], %1;"
                 :: "r"(a), "r"(bytes) : "memory");
}
__device__ __forceinline__ void bulk_cp(uint32_t dst, const void* src,
                                        uint32_t bytes, uint32_t mbar) {
    asm volatile(
        "cp.async.bulk.shared::cta.global.mbarrier::complete_tx::bytes [%0], [%1], %2, [%3];"
        :: "r"(dst), "l"(src), "r"(bytes), "r"(mbar) : "memory");
}
__device__ __forceinline__ void mma_f16_ss(uint32_t d, uint64_t ad, uint64_t bd,
                                           uint32_t idesc, bool acc) {
    uint32_t en = acc ? 1u : 0u;
    asm volatile(
        "{\n\t.reg .pred p;\n\tsetp.ne.u32 p, %5, 0;\n\t"
        "tcgen05.mma.cta_group::1.kind::f16 [%0], %1, %2, %3, {%4, %4, %4, %4}, p;\n\t}"
        :: "r"(d), "l"(ad), "l"(bd), "r"(idesc), "r"(0u), "r"(en) : "memory");
}
__device__ __forceinline__ void tc_commit(uint32_t mbar) {
    asm volatile(
        "tcgen05.commit.cta_group::1.mbarrier::arrive::one.shared::cluster.b64 [%0];"
        :: "r"(mbar) : "memory");
}
__device__ __forceinline__ uint64_t mk_desc(uint32_t addr) {
    constexpr uint64_t BASE = (uint64_t(2) << 61) | (uint64_t(1) << 46) |
                              (uint64_t(64) << 32) | (uint64_t(1) << 16);
    return BASE | ((uint64_t)(addr >> 4) & 0x3FFF);
}
#define TC_ALLOC(sm, n)   asm volatile("tcgen05.alloc.cta_group::1.sync.aligned.shared::cta.b32 [%0], %1;" :: "r"(sm), "r"(n) : "memory")
#define TC_DEALLOC(t, n)  asm volatile("tcgen05.dealloc.cta_group::1.sync.aligned.b32 %0, %1;" :: "r"(t), "r"(n))
#define TC_RELINQ()       asm volatile("tcgen05.relinquish_alloc_permit.cta_group::1.sync.aligned;")
#define TC_FENCE_AFTER()  asm volatile("tcgen05.fence::after_thread_sync;" ::: "memory")
#define TC_FENCE_BEFORE() asm volatile("tcgen05.fence::before_thread_sync;" ::: "memory")
#define TC_WAIT_LD()      asm volatile("tcgen05.wait::ld.sync.aligned;" ::: "memory")

#define LDTM_X32(r, a) \
    asm volatile("tcgen05.ld.sync.aligned.32x32b.x32.b32 " \
        "{%0,%1,%2,%3,%4,%5,%6,%7,%8,%9,%10,%11,%12,%13,%14,%15," \
        "%16,%17,%18,%19,%20,%21,%22,%23,%24,%25,%26,%27,%28,%29,%30,%31}, [%32];" \
        : "=r"((r)[0]),"=r"((r)[1]),"=r"((r)[2]),"=r"((r)[3]),"=r"((r)[4]),"=r"((r)[5]), \
          "=r"((r)[6]),"=r"((r)[7]),"=r"((r)[8]),"=r"((r)[9]),"=r"((r)[10]),"=r"((r)[11]), \
          "=r"((r)[12]),"=r"((r)[13]),"=r"((r)[14]),"=r"((r)[15]),"=r"((r)[16]),"=r"((r)[17]), \
          "=r"((r)[18]),"=r"((r)[19]),"=r"((r)[20]),"=r"((r)[21]),"=r"((r)[22]),"=r"((r)[23]), \
          "=r"((r)[24]),"=r"((r)[25]),"=r"((r)[26]),"=r"((r)[27]),"=r"((r)[28]),"=r"((r)[29]), \
          "=r"((r)[30]),"=r"((r)[31]) : "r"(a))

// ---------------------------------------------------------------------------
// GEMM1 mainloop: 4 stages, lag-1 refill, warp 0 only (unchanged from best).
// ---------------------------------------------------------------------------
__device__ __forceinline__ uint32_t gemm_mainloop_tma(
    const char* At, size_t a0, const char* Bt, size_t b0, int tiles, uint32_t sb)
{
    const int tid = threadIdx.x;
    const int wid = tid >> 5;

    if (wid == 0) TC_ALLOC(sb, 256);
    if (tid == 0) {
        #pragma unroll
        for (int s = 0; s < 4; ++s) {
            mbar_init(sb + 64 + 8 * s, 1);    // full
            mbar_init(sb + 128 + 8 * s, 1);   // done
        }
        asm volatile("fence.proxy.async.shared::cta;" ::: "memory");
    }
    __syncthreads();
    if (wid == 0) TC_RELINQ();
    uint32_t tmem;
    asm volatile("ld.shared.b32 %0, [%1];" : "=r"(tmem) : "r"(sb));

    if (wid == 0) {
        const bool el = elect_one();
        if (el) {
            #pragma unroll
            for (int i = 0; i < 4; ++i) {
                const uint32_t stage = sb + SM_TILES + i * STAGE1_BYTES;
                mbar_expect_tx(sb + 64 + 8 * i, STAGE1_BYTES);
                bulk_cp(stage,          At + (a0 + i) * A_TILE, A_TILE, sb + 64 + 8 * i);
                bulk_cp(stage + A_TILE, Bt + (b0 + i) * B_TILE, B_TILE, sb + 64 + 8 * i);
            }
        }
        uint32_t fph = 0, dph = 0;
        for (int kt = 0; kt < tiles; ++kt) {
            const int s = kt & 3;
            mbar_wait(sb + 64 + 8 * s, (fph >> s) & 1u);
            fph ^= 1u << s;
            asm volatile("fence.proxy.async.shared::cta;" ::: "memory");
            if (el) {
                const uint32_t stage = sb + SM_TILES + s * STAGE1_BYTES;
                const uint64_t ad = mk_desc(stage);
                const uint64_t bd = mk_desc(stage + A_TILE);
                #pragma unroll
                for (int ks = 0; ks < 4; ++ks)
                    mma_f16_ss(tmem, ad + 2 * ks, bd + 2 * ks, IDESC, (kt > 0) || ks > 0);
                tc_commit(sb + 128 + 8 * s);
                if (kt >= 1 && kt + 3 < tiles) {   // lag-1 refill
                    const int sr = (kt - 1) & 3;
                    const uint32_t rstage = sb + SM_TILES + sr * STAGE1_BYTES;
                    mbar_wait(sb + 128 + 8 * sr, (dph >> sr) & 1u);
                    dph ^= 1u << sr;
                    mbar_expect_tx(sb + 64 + 8 * sr, STAGE1_BYTES);
                    bulk_cp(rstage,          At + (a0 + kt + 3) * A_TILE, A_TILE, sb + 64 + 8 * sr);
                    bulk_cp(rstage + A_TILE, Bt + (b0 + kt + 3) * B_TILE, B_TILE, sb + 64 + 8 * sr);
                }
            }
        }
        if (el) {
            const int sl = (tiles - 1) & 3;
            mbar_wait(sb + 128 + 8 * sl, (dph >> sl) & 1u);
        }
    }
    __syncthreads();
    TC_FENCE_AFTER();
    return tmem;
}

// ---------------------------------------------------------------------------
// GEMM2 mainloop: dual accumulator, 3 stages of 64KB, lag-1 refill (unchanged).
// ---------------------------------------------------------------------------
__device__ __forceinline__ uint32_t gemm2_mainloop_tma(
    const char* At, size_t a00, size_t a01, const char* Bt, size_t b0,
    int tiles, uint32_t sb)
{
    const int tid = threadIdx.x;
    const int wid = tid >> 5;

    if (wid == 0) TC_ALLOC(sb, 512);
    if (tid == 0) {
        #pragma unroll
        for (int s = 0; s < 3; ++s) {
            mbar_init(sb + 64 + 8 * s, 1);    // full
            mbar_init(sb + 128 + 8 * s, 1);   // done
        }
        asm volatile("fence.proxy.async.shared::cta;" ::: "memory");
    }
    __syncthreads();
    if (wid == 0) TC_RELINQ();
    uint32_t tmem;
    asm volatile("ld.shared.b32 %0, [%1];" : "=r"(tmem) : "r"(sb));

    if (wid == 0) {
        const bool el = elect_one();
        if (el) {
            #pragma unroll
            for (int i = 0; i < 3; ++i) {
                const uint32_t stage = sb + SM_TILES + i * STAGE2_BYTES;
                mbar_expect_tx(sb + 64 + 8 * i, STAGE2_BYTES);
                bulk_cp(stage,              At + (a00 + i) * A_TILE, A_TILE, sb + 64 + 8 * i);
                bulk_cp(stage + A_TILE,     At + (a01 + i) * A_TILE, A_TILE, sb + 64 + 8 * i);
                bulk_cp(stage + 2 * A_TILE, Bt + (b0 + i) * B_TILE,  B_TILE, sb + 64 + 8 * i);
            }
        }
        uint32_t fph = 0, dph = 0;
        for (int kt = 0; kt < tiles; ++kt) {
            const int s = kt % 3;
            mbar_wait(sb + 64 + 8 * s, (fph >> s) & 1u);
            fph ^= 1u << s;
            asm volatile("fence.proxy.async.shared::cta;" ::: "memory");
            if (el) {
                const uint32_t stage = sb + SM_TILES + s * STAGE2_BYTES;
                const uint64_t a0d = mk_desc(stage);
                const uint64_t a1d = mk_desc(stage + A_TILE);
                const uint64_t bd  = mk_desc(stage + 2 * A_TILE);
                #pragma unroll
                for (int ks = 0; ks < 4; ++ks)
                    mma_f16_ss(tmem, a0d + 2 * ks, bd + 2 * ks, IDESC, (kt > 0) || ks > 0);
                #pragma unroll
                for (int ks = 0; ks < 4; ++ks)
                    mma_f16_ss(tmem + 256, a1d + 2 * ks, bd + 2 * ks, IDESC, (kt > 0) || ks > 0);
                tc_commit(sb + 128 + 8 * s);
                if (kt >= 1 && kt + 2 < tiles) {   // lag-1 refill
                    const int sr = (kt - 1) % 3;
                    const uint32_t rstage = sb + SM_TILES + sr * STAGE2_BYTES;
                    mbar_wait(sb + 128 + 8 * sr, (dph >> sr) & 1u);
                    dph ^= 1u << sr;
                    mbar_expect_tx(sb + 64 + 8 * sr, STAGE2_BYTES);
                    bulk_cp(rstage,              At + (a00 + kt + 2) * A_TILE, A_TILE, sb + 64 + 8 * sr);
                    bulk_cp(rstage + A_TILE,     At + (a01 + kt + 2) * A_TILE, A_TILE, sb + 64 + 8 * sr);
                    bulk_cp(rstage + 2 * A_TILE, Bt + (b0 + kt + 2) * B_TILE,  B_TILE, sb + 64 + 8 * sr);
                }
            }
        }
        if (el) {
            const int sl = (tiles - 1) % 3;
            mbar_wait(sb + 128 + 8 * sl, (dph >> sl) & 1u);
        }
    }
    __syncthreads();
    TC_FENCE_AFTER();
    return tmem;
}
#endif  // HAS_TC

// ---------------------------------------------------------------------------
// Fallback (non-'a' PTX pass): wmma fp16 reading the TILED+SWIZZLED layout.
// Never executed when sm_103a SASS exists; kept for ptxas legality.
// ---------------------------------------------------------------------------
__device__ __forceinline__ void fb_gemm128(
    const char* At, size_t a0, const char* Bt, size_t b0, int brow_off,
    int K, char* smem, float* Cs)
{
    __half* As = reinterpret_cast<__half*>(smem);
    __half* Bs = reinterpret_cast<__half*>(smem + 128 * 40 * 2);
    const int tid = threadIdx.x;
    const int wid = tid >> 5;
    const int wm = wid & 1, wn = wid >> 1;

    wmma::fragment<wmma::accumulator, 16, 16, 16, float> acc[4][2];
    #pragma unroll
    for (int i = 0; i < 4; i++)
        #pragma unroll
        for (int j = 0; j < 2; j++)
            wmma::fill_fragment(acc[i][j], 0.0f);

    for (int kt = 0; kt < K / 32; ++kt) {
        const int kb = kt * 32;
        #pragma unroll
        for (int i = 0; i < 2; ++i) {
            const int v = tid + i * 256;
            const int r = v >> 2, k0 = kb + (v & 3) * 8;
            const int tile = k0 >> 6, kin = k0 & 63;
            *reinterpret_cast<uint4*>(&As[r * 40 + (v & 3) * 8]) =
                *reinterpret_cast<const uint4*>(
                    At + (a0 + tile) * A_TILE + swz((uint32_t)(r * 128 + kin * 2)));
            *reinterpret_cast<uint4*>(&Bs[r * 40 + (v & 3) * 8]) =
                *reinterpret_cast<const uint4*>(
                    Bt + (b0 + tile) * B_TILE + swz((uint32_t)((brow_off + r) * 128 + kin * 2)));
        }
        __syncthreads();
        #pragma unroll
        for (int kk = 0; kk < 32; kk += 16) {
            wmma::fragment<wmma::matrix_a, 16, 16, 16, __half, wmma::row_major> af[4];
            wmma::fragment<wmma::matrix_b, 16, 16, 16, __half, wmma::col_major> bf[2];
            #pragma unroll
            for (int fm = 0; fm < 4; fm++)
                wmma::load_matrix_sync(af[fm], &As[(wm * 64 + fm * 16) * 40 + kk], 40);
            #pragma unroll
            for (int fn = 0; fn < 2; fn++)
                wmma::load_matrix_sync(bf[fn], &Bs[(wn * 32 + fn * 16) * 40 + kk], 40);
            #pragma unroll
            for (int fm = 0; fm < 4; fm++)
                #pragma unroll
                for (int fn = 0; fn < 2; fn++)
                    wmma::mma_sync(acc[fm][fn], af[fm], bf[fn], acc[fm][fn]);
        }
        __syncthreads();
    }
    #pragma unroll
    for (int fm = 0; fm < 4; fm++)
        #pragma unroll
        for (int fn = 0; fn < 2; fn++)
            wmma::store_matrix_sync(&Cs[(wm * 64 + fm * 16) * 132 + wn * 32 + fn * 16],
                                    acc[fm][fn], 132, wmma::mem_row_major);
    __syncthreads();
}

// ---------------------------------------------------------------------------
// GEMM1: enc = tanh(h @ Wh^T + b1) -> g_enc (fp32, linear) + g_ench (tiled)
// grid: (cb=4, rb=32). Epilogue stages through smem; all gmem I/O coalesced.
// ---------------------------------------------------------------------------
__global__ __launch_bounds__(256) void gemm1_kernel(const float* __restrict__ b1)
{
    extern __shared__ __align__(1024) char smem[];
    const int rb = blockIdx.y;
    const int cb = blockIdx.x;
    const int row0 = rb * TM;
    const int col0 = cb * TN;
    const int tid = threadIdx.x;
    const int wid = tid >> 5;
    const int lane = tid & 31;

#if HAS_TC
    const uint32_t sb = smem_u32(smem);
    const uint32_t tmem = gemm_mainloop_tma((const char*)g_h, (size_t)rb * 128,
                                            (const char*)g_Wh, (size_t)cb * 128,
                                            Nn / TK, sb);
    float* es = reinterpret_cast<float*>(smem + SM_TILES);   // 128 x XP staging
    const int team = wid >> 2;
    const int r = ((wid & 3) << 5) + lane;
    // Phase A: TMEM -> tanh -> smem (lane=row; XP pitch => conflict-free)
    #pragma unroll
    for (int chunk = 0; chunk < 4; ++chunk) {
        const int c0 = team * 128 + chunk * 32;
        uint32_t regs[32];
        LDTM_X32(regs, tmem + c0);
        TC_WAIT_LD();
        #pragma unroll
        for (int j = 0; j < 32; ++j)
            es[r * XP + c0 + j] = tanhf(__uint_as_float(regs[j]) + b1[col0 + c0 + j]);
    }
    TC_FENCE_BEFORE();
    __syncthreads();
    if (wid == 0) TC_DEALLOC(tmem, 256);
    // Phase B: coalesced g_enc stores (float4 along rows)
    #pragma unroll
    for (int i = 0; i < 32; ++i) {
        const int idx = tid + i * 256;
        const int row = idx >> 6, c4 = (idx & 63) << 2;
        float4 v;
        v.x = es[row * XP + c4];     v.y = es[row * XP + c4 + 1];
        v.z = es[row * XP + c4 + 2]; v.w = es[row * XP + c4 + 3];
        *reinterpret_cast<float4*>(&g_enc[(size_t)(row0 + row) * Dn + col0 + c4]) = v;
    }
    // Phase C: coalesced tiled g_ench writes (warp covers one 128B line)
    #pragma unroll
    for (int i = 0; i < 64; ++i) {
        const int idx = tid + i * 256;
        const int row = idx >> 7, p = idx & 127;
        const int c = p * 2;
        const __half2 hv = __floats2half2_rn(es[row * XP + c], es[row * XP + c + 1]);
        const int dt = (col0 + c) >> 6;
        const uint32_t bo = (uint32_t)(row * 128 + (c & 63) * 2);
        *reinterpret_cast<__half2*>(
            (char*)g_ench + (size_t)(rb * 16 + dt) * A_TILE + swz(bo)) = hv;
    }
#else
    float* Cs = reinterpret_cast<float*>(smem);
    for (int hf = 0; hf < 2; ++hf) {
        fb_gemm128((const char*)g_h, (size_t)rb * 128,
                   (const char*)g_Wh, (size_t)cb * 128, hf * 128, Nn, smem, Cs);
        #pragma unroll 4
        for (int t = 0; t < 32; ++t) {
            const int p = tid + t * 256;
            const int r2 = p >> 6, c2 = (p & 63) * 2;
            const int d = col0 + hf * 128 + c2;
            const size_t grow = (size_t)(row0 + r2);
            const float e0 = tanhf(Cs[r2 * 132 + c2]     + b1[d]);
            const float e1 = tanhf(Cs[r2 * 132 + c2 + 1] + b1[d + 1]);
            g_enc[grow * Dn + d]     = e0;
            g_enc[grow * Dn + d + 1] = e1;
            const uint32_t bo = (uint32_t)(r2 * 128 + (d & 63) * 2);
            *reinterpret_cast<__half2*>(
                (char*)g_ench + (size_t)(rb * 16 + (d >> 6)) * A_TILE + swz(bo)) =
                __floats2half2_rn(e0, e1);
        }
        __syncthreads();
    }
#endif
}

// ---------------------------------------------------------------------------
// GEMM2: recon = ench @ Wt^T + b2 (never stored); fused masked-MSE partials.
// grid: (nb=32, rbp=16). x is staged per 128-row half through smem coalesced.
// ---------------------------------------------------------------------------
__global__ __launch_bounds__(256) void gemm2_kernel(
    const float* __restrict__ x, const float* __restrict__ b2)
{
    extern __shared__ __align__(1024) char smem[];
    const int nb = blockIdx.x;
    const int rbp = blockIdx.y;
    const int n0 = nb * TN;
    const int tid = threadIdx.x;
    const int wid = tid >> 5;
    const int lane = tid & 31;

#if HAS_TC
    const uint32_t sb = smem_u32(smem);
    const uint32_t tmem = gemm2_mainloop_tma(
        (const char*)g_ench, (size_t)(2 * rbp) * 16, (size_t)(2 * rbp + 1) * 16,
        (const char*)g_Wt, (size_t)nb * 16, Dn / TK, sb);

    float* xs = reinterpret_cast<float*>(smem + SM_TILES);   // 128 x XP staging
    const int myhalf = wid >> 2;
    const int r = ((wid & 3) << 5) + lane;
    float err = 0.f, cnt = 0.f;
    for (int half = 0; half < 2; ++half) {
        const int row0h = rbp * 256 + half * 128;
        // coalesced x tile load -> smem
        #pragma unroll
        for (int i = 0; i < 32; ++i) {
            const int idx = tid + i * 256;
            const int row = idx >> 6, c4 = (idx & 63) << 2;
            const float4 v = *reinterpret_cast<const float4*>(
                &x[(size_t)(row0h + row) * Nn + n0 + c4]);
            xs[row * XP + c4]     = v.x;
            xs[row * XP + c4 + 1] = v.y;
            xs[row * XP + c4 + 2] = v.z;
            xs[row * XP + c4 + 3] = v.w;
        }
        __syncthreads();
        if (myhalf == half) {
            #pragma unroll
            for (int chunk = 0; chunk < 8; ++chunk) {
                const int c0 = chunk * 32;
                uint32_t regs[32];
                LDTM_X32(regs, tmem + half * 256 + c0);
                TC_WAIT_LD();
                const float* b2r = b2 + n0 + c0;
                #pragma unroll
                for (int j = 0; j < 32; ++j) {
                    const float recon = __uint_as_float(regs[j]) + b2r[j];
                    const float xv = xs[r * XP + c0 + j];
                    if (xv != 0.0f) {
                        const float d = xv - recon;
                        err += d * d;
                        cnt += 1.0f;
                    }
                }
            }
        }
        __syncthreads();
    }
    const size_t grow = (size_t)(rbp * 256 + myhalf * 128 + r);
    g_errp[grow * 64 + nb * 2]     = err;
    g_errp[grow * 64 + nb * 2 + 1] = 0.0f;
    g_cntp[grow * 64 + nb * 2]     = cnt;
    g_cntp[grow * 64 + nb * 2 + 1] = 0.0f;

    TC_FENCE_BEFORE();
    __syncthreads();
    if (wid == 0) TC_DEALLOC(tmem, 512);
#else
    float* Cs = reinterpret_cast<float*>(smem);
    for (int rsub = 0; rsub < 2; ++rsub) {
        const int rb = rbp * 2 + rsub;
        for (int hf = 0; hf < 2; ++hf) {
            fb_gemm128((const char*)g_ench, (size_t)rb * 16,
                       (const char*)g_Wt, (size_t)nb * 16, hf * 128, Dn, smem, Cs);
            for (int rr = 0; rr < 16; ++rr) {
                const int r2 = wid * 16 + rr;
                const size_t brow = (size_t)(rb * 128 + r2);
                float err = 0.f, cnt = 0.f;
                #pragma unroll
                for (int s4 = 0; s4 < 4; ++s4) {
                    const int c = s4 * 32 + lane;
                    const float recon = Cs[r2 * 132 + c] + b2[n0 + hf * 128 + c];
                    const float xv = x[brow * Nn + n0 + hf * 128 + c];
                    if (xv != 0.0f) {
                        const float d = xv - recon;
                        err += d * d;
                        cnt += 1.0f;
                    }
                }
                #pragma unroll
                for (int o = 16; o; o >>= 1) {
                    err += __shfl_xor_sync(0xffffffffu, err, o);
                    cnt += __shfl_xor_sync(0xffffffffu, cnt, o);
                }
                if (lane == 0) {
                    g_errp[brow * 64 + nb * 2 + hf] = err;
                    g_cntp[brow * 64 + nb * 2 + hf] = cnt;
                }
            }
            __syncthreads();
        }
    }
#endif
}

// ---------------------------------------------------------------------------
// Pre-pass: dropout-scale x -> fp16, write g_h in tiled+swizzled layout
// ---------------------------------------------------------------------------
__global__ void conv_h_kernel(const float4* __restrict__ x, const float4* __restrict__ m)
{
    const size_t i = (size_t)blockIdx.x * blockDim.x + threadIdx.x;
    const int row = (int)(i >> 11);
    const int n0 = ((int)i & 2047) * 4;
    const float4 xv = x[i], mv = m[i];
    __half2 h0 = __floats2half2_rn(xv.x * mv.x * DROP_SCALE, xv.y * mv.y * DROP_SCALE);
    __half2 h1 = __floats2half2_rn(xv.z * mv.z * DROP_SCALE, xv.w * mv.w * DROP_SCALE);
    const int rb = row >> 7, r = row & 127;
    const int kt = n0 >> 6, c = n0 & 63;
    const uint32_t bo = (uint32_t)(r * 128 + c * 2);
    char* p = (char*)g_h + (size_t)(rb * 128 + kt) * A_TILE + swz(bo);
    uint2 v;
    v.x = *reinterpret_cast<uint32_t*>(&h0);
    v.y = *reinterpret_cast<uint32_t*>(&h1);
    *reinterpret_cast<uint2*>(p) = v;
}

// W prep: read W once; emit g_Wh (tiled, d-major) and g_Wt (tiled, n-major)
__global__ void wprep_kernel(const float* __restrict__ W)
{
    __shared__ __half t[32][33];
    const int n0 = blockIdx.x * 32, d0 = blockIdx.y * 32;
    const int tx = threadIdx.x, ty = threadIdx.y;
    #pragma unroll
    for (int i = ty; i < 32; i += 8) {
        const int d = d0 + i, n = n0 + tx;
        const __half v = __float2half_rn(W[(size_t)d * Nn + n]);
        const uint32_t bo = (uint32_t)((d & 255) * 128 + (n & 63) * 2);
        *reinterpret_cast<__half*>(
            (char*)g_Wh + (size_t)((d >> 8) * 128 + (n >> 6)) * B_TILE + swz(bo)) = v;
        t[i][tx] = v;
    }
    __syncthreads();
    #pragma unroll
    for (int i = ty; i < 32; i += 8) {
        const int n = n0 + i, d = d0 + tx;
        const uint32_t bo = (uint32_t)((n & 255) * 128 + (d & 63) * 2);
        *reinterpret_cast<__half*>(
            (char*)g_Wt + (size_t)((n >> 8) * 16 + (d >> 6)) * B_TILE + swz(bo)) = t[tx][i];
    }
}

// ---------------------------------------------------------------------------
// LayerNorm over D per row -> out[0 : B*D)
// ---------------------------------------------------------------------------
__global__ __launch_bounds__(256) void ln_kernel(
    const float* __restrict__ gamma, const float* __restrict__ beta,
    float* __restrict__ out)
{
    const int row = blockIdx.x;
    const int tid = threadIdx.x;
    const float* rp = g_enc + (size_t)row * Dn;
    float e[4], s = 0.f, ss = 0.f;
    #pragma unroll
    for (int j = 0; j < 4; j++) {
        e[j] = rp[tid + j * 256];
        s += e[j];
        ss += e[j] * e[j];
    }
    #pragma unroll
    for (int o = 16; o; o >>= 1) {
        s  += __shfl_xor_sync(0xffffffffu, s, o);
        ss += __shfl_xor_sync(0xffffffffu, ss, o);
    }
    __shared__ float r1[8], r2[8];
    __shared__ float sh_mu, sh_rstd;
    if ((tid & 31) == 0) { r1[tid >> 5] = s; r2[tid >> 5] = ss; }
    __syncthreads();
    if (tid == 0) {
        float ts = 0.f, tss = 0.f;
        #pragma unroll
        for (int k = 0; k < 8; k++) { ts += r1[k]; tss += r2[k]; }
        const float mu = ts * (1.0f / Dn);
        const float var = tss * (1.0f / Dn) - mu * mu;
        sh_mu = mu;
        sh_rstd = rsqrtf(var + EPS);
    }
    __syncthreads();
    const float mu = sh_mu, rstd = sh_rstd;
    #pragma unroll
    for (int j = 0; j < 4; j++) {
        const int d = tid + j * 256;
        out[(size_t)row * Dn + d] = (e[j] - mu) * rstd * gamma[d] + beta[d];
    }
}

// ---------------------------------------------------------------------------
// Loss reduction (fixed order, no atomics)
// ---------------------------------------------------------------------------
__global__ void reduce1_kernel()
{
    const int row = blockIdx.x * 128 + threadIdx.x;
    float err = 0.f, cnt = 0.f;
    #pragma unroll 8
    for (int j = 0; j < 64; ++j) {
        err += g_errp[(size_t)row * 64 + j];
        cnt += g_cntp[(size_t)row * 64 + j];
    }
    __shared__ float sh[128];
    sh[threadIdx.x] = err / cnt;
    __syncthreads();
    for (int s = 64; s > 0; s >>= 1) {
        if (threadIdx.x < s) sh[threadIdx.x] += sh[threadIdx.x + s];
        __syncthreads();
    }
    if (threadIdx.x == 0) g_lossp[blockIdx.x] = sh[0];
}

__global__ void reduce2_kernel(float* __restrict__ out)
{
    float v = g_lossp[threadIdx.x];
    #pragma unroll
    for (int o = 16; o; o >>= 1) v += __shfl_xor_sync(0xffffffffu, v, o);
    if (threadIdx.x == 0) out[(size_t)Bn * Dn] = v;
}

// ---------------------------------------------------------------------------
// Entry. Inputs: x, drop_mask, W, b1, b2, gamma, beta.
// Output: final [B, D] then recon_loss scalar at out[B*D].
// ---------------------------------------------------------------------------
extern "C" void kernel_launch(void* const* d_in, const int* in_sizes, int n_in,
                              void* d_out, int out_size)
{
    const float* x     = (const float*)d_in[0];
    const float* mask  = (const float*)d_in[1];
    const float* W     = (const float*)d_in[2];
    const float* b1    = (const float*)d_in[3];
    const float* b2    = (const float*)d_in[4];
    const float* gamma = (const float*)d_in[5];
    const float* beta  = (const float*)d_in[6];
    float* out = (float*)d_out;

    cudaFuncSetAttribute(gemm1_kernel, cudaFuncAttributeMaxDynamicSharedMemorySize, SMEM_BYTES);
    cudaFuncSetAttribute(gemm2_kernel, cudaFuncAttributeMaxDynamicSharedMemorySize, SMEM_BYTES);

    conv_h_kernel<<<(Bn * (Nn / 4)) / 256, 256>>>((const float4*)x, (const float4*)mask);
    wprep_kernel<<<dim3(Nn / 32, Dn / 32), dim3(32, 8)>>>(W);
    gemm1_kernel<<<dim3(Dn / TN, Bn / TM), 256, SMEM_BYTES>>>(b1);
    gemm2_kernel<<<dim3(Nn / TN, Bn / 256), 256, SMEM_BYTES>>>(x, b2);
    ln_kernel<<<Bn, 256>>>(gamma, beta, out);
    reduce1_kernel<<<32, 128>>>();
    reduce2_kernel<<<1, 32>>>(out);
}

// round 17
// speedup vs baseline: 1.8849x; 1.0004x over previous
#include <cuda_runtime.h>
#include <cuda_fp16.h>
#include <mma.h>
#include <cstdint>

using namespace nvcuda;

// Arch-specific (sm_10xa) feature gate: tcgen05/TMEM only exist on 'a' targets.
#if defined(__CUDA_ARCH_FEAT_SM103_ALL) || defined(__CUDA_ARCH_FEAT_SM100_ALL) || defined(__CUDA_ARCH_SPECIFIC__)
#define HAS_TC 1
#else
#define HAS_TC 0
#endif

// Problem constants
constexpr int Bn = 4096;
constexpr int Nn = 8192;
constexpr int Dn = 1024;
constexpr float DROP_SCALE = 1.0f / 0.75f;
constexpr float EPS = 1e-5f;

// tcgen05 tiling. GEMM1: CTA = 128(M) x 256(N), 4 stages of (A 16K + B 32K).
// GEMM2: CTA = 256(M) x 256(N) dual-accumulator, 3 stages of 64KB.
// WARP SPECIALIZATION: warp 0 = consumer (full-wait + MMA + commit only);
// warp 1 = producer (done-waits + TMA bulk loads). The done-waits (paced by
// MMA completion) are off the consumer's critical path; TMA issue overlaps
// MMA issue. Warps 2-7 prefetch the gemm2 epilogue x-tile into L2.
constexpr int TM = 128;
constexpr int TN = 256;
constexpr int TK = 64;
constexpr uint32_t A_TILE = 16384;
constexpr uint32_t B_TILE = 32768;
constexpr uint32_t IDESC = (1u << 4) | ((TN / 8) << 17) | ((TM / 16) << 24);

constexpr uint32_t STAGE1_BYTES = A_TILE + B_TILE;             // 49152 (gemm1)
constexpr uint32_t STAGE2_BYTES = 2 * A_TILE + B_TILE;         // 65536 (gemm2)
constexpr uint32_t SM_TILES = 1024;
constexpr uint32_t SMEM_BYTES = SM_TILES + 4 * STAGE1_BYTES;   // 197632
static_assert(SM_TILES + 3 * STAGE2_BYTES <= SMEM_BYTES, "gemm2 stages fit");
constexpr int XP = 257;   // staging pitch in floats (257 % 32 == 1 -> no conflicts)
static_assert(SM_TILES + 128 * XP * 4 <= SMEM_BYTES, "staging fits");

// Device-global scratch (no cudaMalloc). Tiled fp16 operand arrays:
__device__ __align__(1024) __half g_h[(size_t)Bn * Nn];
__device__ __align__(1024) __half g_Wh[(size_t)Dn * Nn];
__device__ __align__(1024) __half g_Wt[(size_t)Nn * Dn];
__device__ __align__(1024) __half g_ench[(size_t)Bn * Dn];
__device__ float g_enc[(size_t)Bn * Dn];     // linear fp32 enc (for LN)
__device__ float g_errp[(size_t)Bn * 64];
__device__ float g_cntp[(size_t)Bn * 64];
__device__ float g_lossp[32];

__device__ __forceinline__ uint32_t smem_u32(const void* p) {
    uint32_t a;
    asm("{ .reg .u64 t; cvta.to.shared.u64 t, %1; cvt.u32.u64 %0, t; }" : "=r"(a) : "l"(p));
    return a;
}
__device__ __forceinline__ uint32_t swz(uint32_t bo) {        // SW128 swizzle
    return bo ^ ((bo >> 3) & 0x70);
}

#if HAS_TC
// ---------------------------------------------------------------------------
// tcgen05 / TMA helpers (sm_103a only)
// ---------------------------------------------------------------------------
__device__ __forceinline__ bool elect_one() {
    uint32_t pred;
    asm volatile("{\n\t.reg .pred p;\n\telect.sync _|p, 0xFFFFFFFF;\n\tselp.b32 %0, 1, 0, p;\n\t}"
                 : "=r"(pred));
    return pred != 0;
}
__device__ __forceinline__ void mbar_init(uint32_t a, uint32_t cnt) {
    asm volatile("mbarrier.init.shared.b64 [%0], %1;" :: "r"(a), "r"(cnt) : "memory");
}
__device__ __forceinline__ void mbar_wait(uint32_t a, uint32_t parity) {
    asm volatile(
        "{\n\t.reg .pred P;\n\t"
        "WL_%=:\n\t"
        "mbarrier.try_wait.parity.acquire.cta.shared::cta.b64 P, [%0], %1, 0x989680;\n\t"
        "@P bra WD_%=;\n\t"
        "bra WL_%=;\n\t"
        "WD_%=:\n\t}"
        :: "r"(a), "r"(parity) : "memory");
}
__device__ __forceinline__ void mbar_expect_tx(uint32_t a, uint32_t bytes) {
    asm volatile("mbarrier.arrive.expect_tx.shared.b64 _, [%0], %1;"
                 :: "r"(a), "r"(bytes) : "memory");
}
__device__ __forceinline__ void bulk_cp(uint32_t dst, const void* src,
                                        uint32_t bytes, uint32_t mbar) {
    asm volatile(
        "cp.async.bulk.shared::cta.global.mbarrier::complete_tx::bytes [%0], [%1], %2, [%3];"
        :: "r"(dst), "l"(src), "r"(bytes), "r"(mbar) : "memory");
}
__device__ __forceinline__ void mma_f16_ss(uint32_t d, uint64_t ad, uint64_t bd,
                                           uint32_t idesc, bool acc) {
    uint32_t en = acc ? 1u : 0u;
    asm volatile(
        "{\n\t.reg .pred p;\n\tsetp.ne.u32 p, %5, 0;\n\t"
        "tcgen05.mma.cta_group::1.kind::f16 [%0], %1, %2, %3, {%4, %4, %4, %4}, p;\n\t}"
        :: "r"(d), "l"(ad), "l"(bd), "r"(idesc), "r"(0u), "r"(en) : "memory");
}
__device__ __forceinline__ void tc_commit(uint32_t mbar) {
    asm volatile(
        "tcgen05.commit.cta_group::1.mbarrier::arrive::one.shared::cluster.b64 [%0];"
        :: "r"(mbar) : "memory");
}
__device__ __forceinline__ uint64_t mk_desc(uint32_t addr) {
    constexpr uint64_t BASE = (uint64_t(2) << 61) | (uint64_t(1) << 46) |
                              (uint64_t(64) << 32) | (uint64_t(1) << 16);
    return BASE | ((uint64_t)(addr >> 4) & 0x3FFF);
}
#define TC_ALLOC(sm, n)   asm volatile("tcgen05.alloc.cta_group::1.sync.aligned.shared::cta.b32 [%0], %1;" :: "r"(sm), "r"(n) : "memory")
#define TC_DEALLOC(t, n)  asm volatile("tcgen05.dealloc.cta_group::1.sync.aligned.b32 %0, %1;" :: "r"(t), "r"(n))
#define TC_RELINQ()       asm volatile("tcgen05.relinquish_alloc_permit.cta_group::1.sync.aligned;")
#define TC_FENCE_AFTER()  asm volatile("tcgen05.fence::after_thread_sync;" ::: "memory")
#define TC_FENCE_BEFORE() asm volatile("tcgen05.fence::before_thread_sync;" ::: "memory")
#define TC_WAIT_LD()      asm volatile("tcgen05.wait::ld.sync.aligned;" ::: "memory")

#define LDTM_X32(r, a) \
    asm volatile("tcgen05.ld.sync.aligned.32x32b.x32.b32 " \
        "{%0,%1,%2,%3,%4,%5,%6,%7,%8,%9,%10,%11,%12,%13,%14,%15," \
        "%16,%17,%18,%19,%20,%21,%22,%23,%24,%25,%26,%27,%28,%29,%30,%31}, [%32];" \
        : "=r"((r)[0]),"=r"((r)[1]),"=r"((r)[2]),"=r"((r)[3]),"=r"((r)[4]),"=r"((r)[5]), \
          "=r"((r)[6]),"=r"((r)[7]),"=r"((r)[8]),"=r"((r)[9]),"=r"((r)[10]),"=r"((r)[11]), \
          "=r"((r)[12]),"=r"((r)[13]),"=r"((r)[14]),"=r"((r)[15]),"=r"((r)[16]),"=r"((r)[17]), \
          "=r"((r)[18]),"=r"((r)[19]),"=r"((r)[20]),"=r"((r)[21]),"=r"((r)[22]),"=r"((r)[23]), \
          "=r"((r)[24]),"=r"((r)[25]),"=r"((r)[26]),"=r"((r)[27]),"=r"((r)[28]),"=r"((r)[29]), \
          "=r"((r)[30]),"=r"((r)[31]) : "r"(a))

// ---------------------------------------------------------------------------
// GEMM1 mainloop: 4 stages, warp-specialized.
//   warp 0 (consumer): full-wait -> fence -> 4 MMAs -> commit done[s].
//   warp 1 (producer): prologue, then per tile t: done-wait(tile t-4) ->
//                      expect_tx -> 2 bulk loads.  Final done-wait by producer.
// ---------------------------------------------------------------------------
__device__ __forceinline__ uint32_t gemm_mainloop_tma(
    const char* At, size_t a0, const char* Bt, size_t b0, int tiles, uint32_t sb)
{
    const int tid = threadIdx.x;
    const int wid = tid >> 5;

    if (wid == 0) TC_ALLOC(sb, 256);
    if (tid == 0) {
        #pragma unroll
        for (int s = 0; s < 4; ++s) {
            mbar_init(sb + 64 + 8 * s, 1);    // full
            mbar_init(sb + 128 + 8 * s, 1);   // done
        }
        asm volatile("fence.proxy.async.shared::cta;" ::: "memory");
    }
    __syncthreads();
    if (wid == 0) TC_RELINQ();
    uint32_t tmem;
    asm volatile("ld.shared.b32 %0, [%1];" : "=r"(tmem) : "r"(sb));

    if (wid == 0) {               // ---- consumer ----
        const bool el = elect_one();
        uint32_t fph = 0;
        for (int kt = 0; kt < tiles; ++kt) {
            const int s = kt & 3;
            mbar_wait(sb + 64 + 8 * s, (fph >> s) & 1u);
            fph ^= 1u << s;
            asm volatile("fence.proxy.async.shared::cta;" ::: "memory");
            if (el) {
                const uint32_t stage = sb + SM_TILES + s * STAGE1_BYTES;
                const uint64_t ad = mk_desc(stage);
                const uint64_t bd = mk_desc(stage + A_TILE);
                #pragma unroll
                for (int ks = 0; ks < 4; ++ks)
                    mma_f16_ss(tmem, ad + 2 * ks, bd + 2 * ks, IDESC, (kt > 0) || ks > 0);
                tc_commit(sb + 128 + 8 * s);
            }
        }
    } else if (wid == 1) {        // ---- producer ----
        if (elect_one()) {
            #pragma unroll
            for (int i = 0; i < 4; ++i) {     // prologue (tiles >= 4)
                const uint32_t stage = sb + SM_TILES + i * STAGE1_BYTES;
                mbar_expect_tx(sb + 64 + 8 * i, STAGE1_BYTES);
                bulk_cp(stage,          At + (a0 + i) * A_TILE, A_TILE, sb + 64 + 8 * i);
                bulk_cp(stage + A_TILE, Bt + (b0 + i) * B_TILE, B_TILE, sb + 64 + 8 * i);
            }
            uint32_t dph = 0;
            for (int t = 4; t < tiles; ++t) {
                const int s = t & 3;
                mbar_wait(sb + 128 + 8 * s, (dph >> s) & 1u);   // tile t-4 done
                dph ^= 1u << s;
                const uint32_t stage = sb + SM_TILES + s * STAGE1_BYTES;
                mbar_expect_tx(sb + 64 + 8 * s, STAGE1_BYTES);
                bulk_cp(stage,          At + (a0 + t) * A_TILE, A_TILE, sb + 64 + 8 * s);
                bulk_cp(stage + A_TILE, Bt + (b0 + t) * B_TILE, B_TILE, sb + 64 + 8 * s);
            }
            const int sl = (tiles - 1) & 3;   // final: all MMAs done
            mbar_wait(sb + 128 + 8 * sl, (dph >> sl) & 1u);
        }
    }
    __syncthreads();              // release epilogue only after MMAs all done
    TC_FENCE_AFTER();
    return tmem;
}

// ---------------------------------------------------------------------------
// GEMM2 mainloop: dual accumulator, 3 stages of 64KB, warp-specialized.
// Warps 2-7 prefetch the epilogue x tile (256 rows x 1KB) into L2 meanwhile.
// ---------------------------------------------------------------------------
__device__ __forceinline__ uint32_t gemm2_mainloop_tma(
    const char* At, size_t a00, size_t a01, const char* Bt, size_t b0,
    int tiles, uint32_t sb, const float* xpf)
{
    const int tid = threadIdx.x;
    const int wid = tid >> 5;
    const int lane = tid & 31;

    if (wid == 0) TC_ALLOC(sb, 512);
    if (tid == 0) {
        #pragma unroll
        for (int s = 0; s < 3; ++s) {
            mbar_init(sb + 64 + 8 * s, 1);    // full
            mbar_init(sb + 128 + 8 * s, 1);   // done
        }
        asm volatile("fence.proxy.async.shared::cta;" ::: "memory");
    }
    __syncthreads();
    if (wid == 0) TC_RELINQ();
    uint32_t tmem;
    asm volatile("ld.shared.b32 %0, [%1];" : "=r"(tmem) : "r"(sb));

    if (wid == 0) {               // ---- consumer ----
        const bool el = elect_one();
        uint32_t fph = 0;
        for (int kt = 0; kt < tiles; ++kt) {
            const int s = kt % 3;
            mbar_wait(sb + 64 + 8 * s, (fph >> s) & 1u);
            fph ^= 1u << s;
            asm volatile("fence.proxy.async.shared::cta;" ::: "memory");
            if (el) {
                const uint32_t stage = sb + SM_TILES + s * STAGE2_BYTES;
                const uint64_t a0d = mk_desc(stage);
                const uint64_t a1d = mk_desc(stage + A_TILE);
                const uint64_t bd  = mk_desc(stage + 2 * A_TILE);
                #pragma unroll
                for (int ks = 0; ks < 4; ++ks)
                    mma_f16_ss(tmem, a0d + 2 * ks, bd + 2 * ks, IDESC, (kt > 0) || ks > 0);
                #pragma unroll
                for (int ks = 0; ks < 4; ++ks)
                    mma_f16_ss(tmem + 256, a1d + 2 * ks, bd + 2 * ks, IDESC, (kt > 0) || ks > 0);
                tc_commit(sb + 128 + 8 * s);
            }
        }
    } else if (wid == 1) {        // ---- producer ----
        if (elect_one()) {
            #pragma unroll
            for (int i = 0; i < 3; ++i) {     // prologue (tiles >= 3)
                const uint32_t stage = sb + SM_TILES + i * STAGE2_BYTES;
                mbar_expect_tx(sb + 64 + 8 * i, STAGE2_BYTES);
                bulk_cp(stage,              At + (a00 + i) * A_TILE, A_TILE, sb + 64 + 8 * i);
                bulk_cp(stage + A_TILE,     At + (a01 + i) * A_TILE, A_TILE, sb + 64 + 8 * i);
                bulk_cp(stage + 2 * A_TILE, Bt + (b0 + i) * B_TILE,  B_TILE, sb + 64 + 8 * i);
            }
            uint32_t dph = 0;
            for (int t = 3; t < tiles; ++t) {
                const int s = t % 3;
                mbar_wait(sb + 128 + 8 * s, (dph >> s) & 1u);   // tile t-3 done
                dph ^= 1u << s;
                const uint32_t stage = sb + SM_TILES + s * STAGE2_BYTES;
                mbar_expect_tx(sb + 64 + 8 * s, STAGE2_BYTES);
                bulk_cp(stage,              At + (a00 + t) * A_TILE, A_TILE, sb + 64 + 8 * s);
                bulk_cp(stage + A_TILE,     At + (a01 + t) * A_TILE, A_TILE, sb + 64 + 8 * s);
                bulk_cp(stage + 2 * A_TILE, Bt + (b0 + t) * B_TILE,  B_TILE, sb + 64 + 8 * s);
            }
            const int sl = (tiles - 1) % 3;   // final: all MMAs done
            mbar_wait(sb + 128 + 8 * sl, (dph >> sl) & 1u);
        }
    } else {                      // ---- warps 2-7: x L2 prefetch ----
        // 256 rows x 8 lines of 128B each = 2048 prefetches over 192 threads
        for (int idx = (wid - 2) * 32 + lane; idx < 2048; idx += 192) {
            const int row = idx >> 3, li = idx & 7;
            asm volatile("prefetch.global.L2 [%0];"
                         :: "l"(xpf + (size_t)row * Nn + li * 32));
        }
    }
    __syncthreads();
    TC_FENCE_AFTER();
    return tmem;
}
#endif  // HAS_TC

// ---------------------------------------------------------------------------
// Fallback (non-'a' PTX pass): wmma fp16 reading the TILED+SWIZZLED layout.
// ---------------------------------------------------------------------------
__device__ __forceinline__ void fb_gemm128(
    const char* At, size_t a0, const char* Bt, size_t b0, int brow_off,
    int K, char* smem, float* Cs)
{
    __half* As = reinterpret_cast<__half*>(smem);
    __half* Bs = reinterpret_cast<__half*>(smem + 128 * 40 * 2);
    const int tid = threadIdx.x;
    const int wid = tid >> 5;
    const int wm = wid & 1, wn = wid >> 1;

    wmma::fragment<wmma::accumulator, 16, 16, 16, float> acc[4][2];
    #pragma unroll
    for (int i = 0; i < 4; i++)
        #pragma unroll
        for (int j = 0; j < 2; j++)
            wmma::fill_fragment(acc[i][j], 0.0f);

    for (int kt = 0; kt < K / 32; ++kt) {
        const int kb = kt * 32;
        #pragma unroll
        for (int i = 0; i < 2; ++i) {
            const int v = tid + i * 256;
            const int r = v >> 2, k0 = kb + (v & 3) * 8;
            const int tile = k0 >> 6, kin = k0 & 63;
            *reinterpret_cast<uint4*>(&As[r * 40 + (v & 3) * 8]) =
                *reinterpret_cast<const uint4*>(
                    At + (a0 + tile) * A_TILE + swz((uint32_t)(r * 128 + kin * 2)));
            *reinterpret_cast<uint4*>(&Bs[r * 40 + (v & 3) * 8]) =
                *reinterpret_cast<const uint4*>(
                    Bt + (b0 + tile) * B_TILE + swz((uint32_t)((brow_off + r) * 128 + kin * 2)));
        }
        __syncthreads();
        #pragma unroll
        for (int kk = 0; kk < 32; kk += 16) {
            wmma::fragment<wmma::matrix_a, 16, 16, 16, __half, wmma::row_major> af[4];
            wmma::fragment<wmma::matrix_b, 16, 16, 16, __half, wmma::col_major> bf[2];
            #pragma unroll
            for (int fm = 0; fm < 4; fm++)
                wmma::load_matrix_sync(af[fm], &As[(wm * 64 + fm * 16) * 40 + kk], 40);
            #pragma unroll
            for (int fn = 0; fn < 2; fn++)
                wmma::load_matrix_sync(bf[fn], &Bs[(wn * 32 + fn * 16) * 40 + kk], 40);
            #pragma unroll
            for (int fm = 0; fm < 4; fm++)
                #pragma unroll
                for (int fn = 0; fn < 2; fn++)
                    wmma::mma_sync(acc[fm][fn], af[fm], bf[fn], acc[fm][fn]);
        }
        __syncthreads();
    }
    #pragma unroll
    for (int fm = 0; fm < 4; fm++)
        #pragma unroll
        for (int fn = 0; fn < 2; fn++)
            wmma::store_matrix_sync(&Cs[(wm * 64 + fm * 16) * 132 + wn * 32 + fn * 16],
                                    acc[fm][fn], 132, wmma::mem_row_major);
    __syncthreads();
}

// ---------------------------------------------------------------------------
// GEMM1: enc = tanh(h @ Wh^T + b1) -> g_enc (fp32, linear) + g_ench (tiled)
// grid: (cb=4, rb=32). Epilogue staged through smem; all gmem I/O coalesced.
// ---------------------------------------------------------------------------
__global__ __launch_bounds__(256) void gemm1_kernel(const float* __restrict__ b1)
{
    extern __shared__ __align__(1024) char smem[];
    const int rb = blockIdx.y;
    const int cb = blockIdx.x;
    const int row0 = rb * TM;
    const int col0 = cb * TN;
    const int tid = threadIdx.x;
    const int wid = tid >> 5;
    const int lane = tid & 31;

#if HAS_TC
    const uint32_t sb = smem_u32(smem);
    const uint32_t tmem = gemm_mainloop_tma((const char*)g_h, (size_t)rb * 128,
                                            (const char*)g_Wh, (size_t)cb * 128,
                                            Nn / TK, sb);
    float* es = reinterpret_cast<float*>(smem + SM_TILES);   // 128 x XP staging
    const int team = wid >> 2;
    const int r = ((wid & 3) << 5) + lane;
    // Phase A: TMEM -> tanh -> smem (lane=row; XP pitch => conflict-free)
    #pragma unroll
    for (int chunk = 0; chunk < 4; ++chunk) {
        const int c0 = team * 128 + chunk * 32;
        uint32_t regs[32];
        LDTM_X32(regs, tmem + c0);
        TC_WAIT_LD();
        #pragma unroll
        for (int j = 0; j < 32; ++j)
            es[r * XP + c0 + j] = tanhf(__uint_as_float(regs[j]) + b1[col0 + c0 + j]);
    }
    TC_FENCE_BEFORE();
    __syncthreads();
    if (wid == 0) TC_DEALLOC(tmem, 256);
    // Phase B: coalesced g_enc stores (float4 along rows)
    #pragma unroll
    for (int i = 0; i < 32; ++i) {
        const int idx = tid + i * 256;
        const int row = idx >> 6, c4 = (idx & 63) << 2;
        float4 v;
        v.x = es[row * XP + c4];     v.y = es[row * XP + c4 + 1];
        v.z = es[row * XP + c4 + 2]; v.w = es[row * XP + c4 + 3];
        *reinterpret_cast<float4*>(&g_enc[(size_t)(row0 + row) * Dn + col0 + c4]) = v;
    }
    // Phase C: coalesced tiled g_ench writes (warp covers one 128B line)
    #pragma unroll
    for (int i = 0; i < 64; ++i) {
        const int idx = tid + i * 256;
        const int row = idx >> 7, p = idx & 127;
        const int c = p * 2;
        const __half2 hv = __floats2half2_rn(es[row * XP + c], es[row * XP + c + 1]);
        const int dt = (col0 + c) >> 6;
        const uint32_t bo = (uint32_t)(row * 128 + (c & 63) * 2);
        *reinterpret_cast<__half2*>(
            (char*)g_ench + (size_t)(rb * 16 + dt) * A_TILE + swz(bo)) = hv;
    }
#else
    float* Cs = reinterpret_cast<float*>(smem);
    for (int hf = 0; hf < 2; ++hf) {
        fb_gemm128((const char*)g_h, (size_t)rb * 128,
                   (const char*)g_Wh, (size_t)cb * 128, hf * 128, Nn, smem, Cs);
        #pragma unroll 4
        for (int t = 0; t < 32; ++t) {
            const int p = tid + t * 256;
            const int r2 = p >> 6, c2 = (p & 63) * 2;
            const int d = col0 + hf * 128 + c2;
            const size_t grow = (size_t)(row0 + r2);
            const float e0 = tanhf(Cs[r2 * 132 + c2]     + b1[d]);
            const float e1 = tanhf(Cs[r2 * 132 + c2 + 1] + b1[d + 1]);
            g_enc[grow * Dn + d]     = e0;
            g_enc[grow * Dn + d + 1] = e1;
            const uint32_t bo = (uint32_t)(r2 * 128 + (d & 63) * 2);
            *reinterpret_cast<__half2*>(
                (char*)g_ench + (size_t)(rb * 16 + (d >> 6)) * A_TILE + swz(bo)) =
                __floats2half2_rn(e0, e1);
        }
        __syncthreads();
    }
#endif
}

// ---------------------------------------------------------------------------
// GEMM2: recon = ench @ Wt^T + b2 (never stored); fused masked-MSE partials.
// grid: (nb=32, rbp=16). x staged per 128-row half through smem, coalesced;
// x tile is L2-prefetched by warps 2-7 during the mainloop.
// ---------------------------------------------------------------------------
__global__ __launch_bounds__(256) void gemm2_kernel(
    const float* __restrict__ x, const float* __restrict__ b2)
{
    extern __shared__ __align__(1024) char smem[];
    const int nb = blockIdx.x;
    const int rbp = blockIdx.y;
    const int n0 = nb * TN;
    const int tid = threadIdx.x;
    const int wid = tid >> 5;
    const int lane = tid & 31;

#if HAS_TC
    const uint32_t sb = smem_u32(smem);
    const uint32_t tmem = gemm2_mainloop_tma(
        (const char*)g_ench, (size_t)(2 * rbp) * 16, (size_t)(2 * rbp + 1) * 16,
        (const char*)g_Wt, (size_t)nb * 16, Dn / TK, sb,
        x + (size_t)(rbp * 256) * Nn + n0);

    float* xs = reinterpret_cast<float*>(smem + SM_TILES);   // 128 x XP staging
    const int myhalf = wid >> 2;
    const int r = ((wid & 3) << 5) + lane;
    float err = 0.f, cnt = 0.f;
    for (int half = 0; half < 2; ++half) {
        const int row0h = rbp * 256 + half * 128;
        #pragma unroll
        for (int i = 0; i < 32; ++i) {                        // coalesced x -> smem
            const int idx = tid + i * 256;
            const int row = idx >> 6, c4 = (idx & 63) << 2;
            const float4 v = *reinterpret_cast<const float4*>(
                &x[(size_t)(row0h + row) * Nn + n0 + c4]);
            xs[row * XP + c4]     = v.x;
            xs[row * XP + c4 + 1] = v.y;
            xs[row * XP + c4 + 2] = v.z;
            xs[row * XP + c4 + 3] = v.w;
        }
        __syncthreads();
        if (myhalf == half) {
            #pragma unroll
            for (int chunk = 0; chunk < 8; ++chunk) {
                const int c0 = chunk * 32;
                uint32_t regs[32];
                LDTM_X32(regs, tmem + half * 256 + c0);
                TC_WAIT_LD();
                const float* b2r = b2 + n0 + c0;
                #pragma unroll
                for (int j = 0; j < 32; ++j) {
                    const float recon = __uint_as_float(regs[j]) + b2r[j];
                    const float xv = xs[r * XP + c0 + j];
                    if (xv != 0.0f) {
                        const float d = xv - recon;
                        err += d * d;
                        cnt += 1.0f;
                    }
                }
            }
        }
        __syncthreads();
    }
    const size_t grow = (size_t)(rbp * 256 + myhalf * 128 + r);
    g_errp[grow * 64 + nb * 2]     = err;
    g_errp[grow * 64 + nb * 2 + 1] = 0.0f;
    g_cntp[grow * 64 + nb * 2]     = cnt;
    g_cntp[grow * 64 + nb * 2 + 1] = 0.0f;

    TC_FENCE_BEFORE();
    __syncthreads();
    if (wid == 0) TC_DEALLOC(tmem, 512);
#else
    float* Cs = reinterpret_cast<float*>(smem);
    for (int rsub = 0; rsub < 2; ++rsub) {
        const int rb = rbp * 2 + rsub;
        for (int hf = 0; hf < 2; ++hf) {
            fb_gemm128((const char*)g_ench, (size_t)rb * 16,
                       (const char*)g_Wt, (size_t)nb * 16, hf * 128, Dn, smem, Cs);
            for (int rr = 0; rr < 16; ++rr) {
                const int r2 = wid * 16 + rr;
                const size_t brow = (size_t)(rb * 128 + r2);
                float err = 0.f, cnt = 0.f;
                #pragma unroll
                for (int s4 = 0; s4 < 4; ++s4) {
                    const int c = s4 * 32 + lane;
                    const float recon = Cs[r2 * 132 + c] + b2[n0 + hf * 128 + c];
                    const float xv = x[brow * Nn + n0 + hf * 128 + c];
                    if (xv != 0.0f) {
                        const float d = xv - recon;
                        err += d * d;
                        cnt += 1.0f;
                    }
                }
                #pragma unroll
                for (int o = 16; o; o >>= 1) {
                    err += __shfl_xor_sync(0xffffffffu, err, o);
                    cnt += __shfl_xor_sync(0xffffffffu, cnt, o);
                }
                if (lane == 0) {
                    g_errp[brow * 64 + nb * 2 + hf] = err;
                    g_cntp[brow * 64 + nb * 2 + hf] = cnt;
                }
            }
            __syncthreads();
        }
    }
#endif
}

// ---------------------------------------------------------------------------
// Pre-pass: dropout-scale x -> fp16, write g_h in tiled+swizzled layout
// ---------------------------------------------------------------------------
__global__ void conv_h_kernel(const float4* __restrict__ x, const float4* __restrict__ m)
{
    const size_t i = (size_t)blockIdx.x * blockDim.x + threadIdx.x;
    const int row = (int)(i >> 11);
    const int n0 = ((int)i & 2047) * 4;
    const float4 xv = x[i], mv = m[i];
    __half2 h0 = __floats2half2_rn(xv.x * mv.x * DROP_SCALE, xv.y * mv.y * DROP_SCALE);
    __half2 h1 = __floats2half2_rn(xv.z * mv.z * DROP_SCALE, xv.w * mv.w * DROP_SCALE);
    const int rb = row >> 7, r = row & 127;
    const int kt = n0 >> 6, c = n0 & 63;
    const uint32_t bo = (uint32_t)(r * 128 + c * 2);
    char* p = (char*)g_h + (size_t)(rb * 128 + kt) * A_TILE + swz(bo);
    uint2 v;
    v.x = *reinterpret_cast<uint32_t*>(&h0);
    v.y = *reinterpret_cast<uint32_t*>(&h1);
    *reinterpret_cast<uint2*>(p) = v;
}

// W prep: read W once; emit g_Wh (tiled, d-major) and g_Wt (tiled, n-major)
__global__ void wprep_kernel(const float* __restrict__ W)
{
    __shared__ __half t[32][33];
    const int n0 = blockIdx.x * 32, d0 = blockIdx.y * 32;
    const int tx = threadIdx.x, ty = threadIdx.y;
    #pragma unroll
    for (int i = ty; i < 32; i += 8) {
        const int d = d0 + i, n = n0 + tx;
        const __half v = __float2half_rn(W[(size_t)d * Nn + n]);
        const uint32_t bo = (uint32_t)((d & 255) * 128 + (n & 63) * 2);
        *reinterpret_cast<__half*>(
            (char*)g_Wh + (size_t)((d >> 8) * 128 + (n >> 6)) * B_TILE + swz(bo)) = v;
        t[i][tx] = v;
    }
    __syncthreads();
    #pragma unroll
    for (int i = ty; i < 32; i += 8) {
        const int n = n0 + i, d = d0 + tx;
        const uint32_t bo = (uint32_t)((n & 255) * 128 + (d & 63) * 2);
        *reinterpret_cast<__half*>(
            (char*)g_Wt + (size_t)((n >> 8) * 16 + (d >> 6)) * B_TILE + swz(bo)) = t[tx][i];
    }
}

// ---------------------------------------------------------------------------
// LayerNorm over D per row -> out[0 : B*D)
// ---------------------------------------------------------------------------
__global__ __launch_bounds__(256) void ln_kernel(
    const float* __restrict__ gamma, const float* __restrict__ beta,
    float* __restrict__ out)
{
    const int row = blockIdx.x;
    const int tid = threadIdx.x;
    const float* rp = g_enc + (size_t)row * Dn;
    float e[4], s = 0.f, ss = 0.f;
    #pragma unroll
    for (int j = 0; j < 4; j++) {
        e[j] = rp[tid + j * 256];
        s += e[j];
        ss += e[j] * e[j];
    }
    #pragma unroll
    for (int o = 16; o; o >>= 1) {
        s  += __shfl_xor_sync(0xffffffffu, s, o);
        ss += __shfl_xor_sync(0xffffffffu, ss, o);
    }
    __shared__ float r1[8], r2[8];
    __shared__ float sh_mu, sh_rstd;
    if ((tid & 31) == 0) { r1[tid >> 5] = s; r2[tid >> 5] = ss; }
    __syncthreads();
    if (tid == 0) {
        float ts = 0.f, tss = 0.f;
        #pragma unroll
        for (int k = 0; k < 8; k++) { ts += r1[k]; tss += r2[k]; }
        const float mu = ts * (1.0f / Dn);
        const float var = tss * (1.0f / Dn) - mu * mu;
        sh_mu = mu;
        sh_rstd = rsqrtf(var + EPS);
    }
    __syncthreads();
    const float mu = sh_mu, rstd = sh_rstd;
    #pragma unroll
    for (int j = 0; j < 4; j++) {
        const int d = tid + j * 256;
        out[(size_t)row * Dn + d] = (e[j] - mu) * rstd * gamma[d] + beta[d];
    }
}

// ---------------------------------------------------------------------------
// Loss reduction (fixed order, no atomics)
// ---------------------------------------------------------------------------
__global__ void reduce1_kernel()
{
    const int row = blockIdx.x * 128 + threadIdx.x;
    float err = 0.f, cnt = 0.f;
    #pragma unroll 8
    for (int j = 0; j < 64; ++j) {
        err += g_errp[(size_t)row * 64 + j];
        cnt += g_cntp[(size_t)row * 64 + j];
    }
    __shared__ float sh[128];
    sh[threadIdx.x] = err / cnt;
    __syncthreads();
    for (int s = 64; s > 0; s >>= 1) {
        if (threadIdx.x < s) sh[threadIdx.x] += sh[threadIdx.x + s];
        __syncthreads();
    }
    if (threadIdx.x == 0) g_lossp[blockIdx.x] = sh[0];
}

__global__ void reduce2_kernel(float* __restrict__ out)
{
    float v = g_lossp[threadIdx.x];
    #pragma unroll
    for (int o = 16; o; o >>= 1) v += __shfl_xor_sync(0xffffffffu, v, o);
    if (threadIdx.x == 0) out[(size_t)Bn * Dn] = v;
}

// ---------------------------------------------------------------------------
// Entry. Inputs: x, drop_mask, W, b1, b2, gamma, beta.
// Output: final [B, D] then recon_loss scalar at out[B*D].
// ---------------------------------------------------------------------------
extern "C" void kernel_launch(void* const* d_in, const int* in_sizes, int n_in,
                              void* d_out, int out_size)
{
    const float* x     = (const float*)d_in[0];
    const float* mask  = (const float*)d_in[1];
    const float* W     = (const float*)d_in[2];
    const float* b1    = (const float*)d_in[3];
    const float* b2    = (const float*)d_in[4];
    const float* gamma = (const float*)d_in[5];
    const float* beta  = (const float*)d_in[6];
    float* out = (float*)d_out;

    cudaFuncSetAttribute(gemm1_kernel, cudaFuncAttributeMaxDynamicSharedMemorySize, SMEM_BYTES);
    cudaFuncSetAttribute(gemm2_kernel, cudaFuncAttributeMaxDynamicSharedMemorySize, SMEM_BYTES);

    conv_h_kernel<<<(Bn * (Nn / 4)) / 256, 256>>>((const float4*)x, (const float4*)mask);
    wprep_kernel<<<dim3(Nn / 32, Dn / 32), dim3(32, 8)>>>(W);
    gemm1_kernel<<<dim3(Dn / TN, Bn / TM), 256, SMEM_BYTES>>>(b1);
    gemm2_kernel<<<dim3(Nn / TN, Bn / 256), 256, SMEM_BYTES>>>(x, b2);
    ln_kernel<<<Bn, 256>>>(gamma, beta, out);
    reduce1_kernel<<<32, 128>>>();
    reduce2_kernel<<<1, 32>>>(out);
}